// round 13
// baseline (speedup 1.0000x reference)
#include <cuda_runtime.h>
#include <math.h>

#define BB 8
#define VV 2048
#define DD 16
#define FF 64
#define EMBD 32
#define HID 32
#define FEAT 16
#define BV (BB*VV)            // 16384
#define BVD (BV*DD)           // 262144
#define VD (VV*DD)            // 32768
#define NC (BV+1)             // 16385 classes (+1 global masked class)
#define NCPAD (65*256)        // 16640
#define BIGC 1e9f

typedef unsigned long long ull;

// ---------------- packed f32x2 helpers ----------------------------------------
__device__ __forceinline__ ull pack2(float lo, float hi){
    ull r;
    asm("mov.b64 %0, {%1, %2};" : "=l"(r) : "f"(lo), "f"(hi));
    return r;
}
__device__ __forceinline__ void unpack2(ull v, float& lo, float& hi){
    asm("mov.b64 {%0, %1}, %2;" : "=f"(lo), "=f"(hi) : "l"(v));
}
__device__ __forceinline__ void fma2(ull& d, ull a, ull b){
    asm("fma.rn.f32x2 %0, %1, %2, %0;" : "+l"(d) : "l"(a), "l"(b));
}
// ---------------- PDL helpers ---------------------------------------------------
__device__ __forceinline__ void pdl_trigger(){ asm volatile("griddepcontrol.launch_dependents;" ::: "memory"); }
__device__ __forceinline__ void pdl_wait(){ asm volatile("griddepcontrol.wait;" ::: "memory"); }

// ---------------- scratch (device globals) -----------------------------------
__device__ float g_enc[BV*FF];
__device__ float g_S[NCPAD*FF];      // per-class state
__device__ float g_H[NCPAD*FF];      // per-class tanh(state@W+b)
__device__ float g_sc[NCPAD];        // per-class gat score
__device__ float g_agg[BV*FF];       // per-node agg
__device__ float g_nwc[NCPAD];       // per-class decoder output
__device__ float g_attnin[BVD];
__device__ float g_norm[BVD];
__device__ float g_ns[BV*FF];
__device__ float g_dualvars[BV];
__device__ float g_fc[BB];
__device__ float g_dq[BVD/256];

// ---------------- 1. fused emb-normalize + encoder + S init -------------------
__global__ void k_enc(const float* __restrict__ nf, const float* __restrict__ emb,
                      const float* __restrict__ W, const float* __restrict__ bvec){
    pdl_trigger();
    if (blockIdx.x >= BV/4){
        int i = (blockIdx.x - BV/4)*256 + threadIdx.x;     // float4 units, 4096 total
        ((float4*)(g_S + (size_t)BV*FF))[i] = make_float4(0.f,0.f,0.f,0.f);
        return;
    }
    __shared__ float sEmb[4*EMBD];
    int t = threadIdx.x;
    int w = t >> 5, lane = t & 31;
    if (w < 4){
        int v = (blockIdx.x*4 + w) & (VV-1);
        float x = emb[v*EMBD + lane];
        float s = x*x;
        #pragma unroll
        for (int o=16;o;o>>=1) s += __shfl_xor_sync(0xffffffffu, s, o);
        float nrm = sqrtf(s);
        float scale = fminf(1.0f, 1.0f / fmaxf(nrm, 1e-12f));
        sEmb[w*EMBD + lane] = x*scale;
    }
    __syncthreads();
    int nl = t >> 6, f = t & 63;
    int node = blockIdx.x*4 + nl;
    float acc = bvec[f];
    const float* ev = sEmb + nl*EMBD;
    const float* nr = nf + node*FEAT;
    #pragma unroll
    for (int k=0;k<EMBD;k++) acc += ev[k]*W[k*FF+f];
    #pragma unroll
    for (int k=0;k<FEAT;k++) acc += nr[k]*W[(EMBD+k)*FF+f];
    g_enc[node*FF+f] = acc;
    g_S[(size_t)node*FF+f] = acc;
}

// ---------------- 2. per-class GAT: H = tanh(S@W+b), sc = H.a ------------------
// 128 rows/block, 512 threads: 4 threads per row, each 2 f-chunks of 8.
#define GAT_SMEM ((64*64 + 128*64) * (int)sizeof(float))
__global__ void __launch_bounds__(512) k_gat(const float* __restrict__ W,
                                             const float* __restrict__ bvec,
                                             const float* __restrict__ gat_a){
    extern __shared__ float sh[];
    float* Ws   = sh;                 // 64*64
    float* tile = sh + 64*64;         // 128*64 swizzled
    __shared__ float scpart[512];
    int t = threadIdx.x;
    size_t base = (size_t)blockIdx.x * 128;
    for (int i=t;i<64*64;i+=512) Ws[i] = W[i];     // independent prologue
    pdl_wait();                                     // g_S writer must be complete
    for (int i=t;i<128*64;i+=512){
        int row = i>>6, k = i&63;
        tile[(row<<6) | (k ^ (row&31))] = g_S[base*FF + i];
    }
    __syncthreads();
    pdl_trigger();
    int row = t & 127, quarter = t >> 7;
    const float* srow = tile + (row<<6);
    int c = row & 31;
    size_t orow = (base + row) * FF;
    bool live = (base + row) < NC;
    float sc = 0.f;
    #pragma unroll
    for (int fo=0; fo<2; fo++){
        int f = (quarter*2 + fo)*8;
        ull acc[4];
        {
            float b8[8];
            *(float4*)&b8[0] = __ldg((const float4*)(bvec+f));
            *(float4*)&b8[4] = __ldg((const float4*)(bvec+f+4));
            #pragma unroll
            for (int j=0;j<4;j++) acc[j] = pack2(b8[2*j], b8[2*j+1]);
        }
        #pragma unroll 4
        for (int k=0;k<64;k++){
            float skf = srow[k ^ c];
            ull sk2 = pack2(skf, skf);
            const ulonglong2* wp = (const ulonglong2*)(Ws + k*64 + f);
            ulonglong2 w01 = wp[0], w23 = wp[1];
            fma2(acc[0], w01.x, sk2);
            fma2(acc[1], w01.y, sk2);
            fma2(acc[2], w23.x, sk2);
            fma2(acc[3], w23.y, sk2);
        }
        float av[8], hv[8];
        *(float4*)&av[0] = __ldg((const float4*)(gat_a+f));
        *(float4*)&av[4] = __ldg((const float4*)(gat_a+f+4));
        #pragma unroll
        for (int j=0;j<4;j++){
            float a0,a1; unpack2(acc[j], a0, a1);
            hv[2*j]   = tanhf(a0);
            hv[2*j+1] = tanhf(a1);
            sc += hv[2*j]*av[2*j] + hv[2*j+1]*av[2*j+1];
        }
        if (live){
            *(float4*)(g_H + orow + f)     = *(float4*)&hv[0];
            *(float4*)(g_H + orow + f + 4) = *(float4*)&hv[4];
        }
    }
    scpart[t] = sc;
    __syncthreads();
    if (t < 128 && (base + t) < NC)
        g_sc[base + t] = (scpart[t] + scpart[t+128]) + (scpart[t+256] + scpart[t+384]);
}

// ---------------- 3. per-node softmax(D) + agg from class rows ------------------
__global__ void k_attnagg(const int* __restrict__ adj, const int* __restrict__ num_nodes){
    pdl_trigger();
    pdl_wait();
    int lane = threadIdx.x & 31;
    int node = blockIdx.x*8 + (threadIdx.x >> 5);
    int b = node >> 11;
    int nn = num_nodes[b];
    int c = 0;
    float sc = -1e30f;
    if (lane < DD){
        int a = adj[node*DD+lane];
        bool m = (a==nn);
        c = m ? BV : ((b<<11)+a);
        sc = g_sc[c] - (m ? BIGC : 0.f);
    }
    float mx = sc;
    #pragma unroll
    for (int o=16;o;o>>=1) mx = fmaxf(mx, __shfl_xor_sync(0xffffffffu, mx, o));
    float e = (lane < DD) ? __expf(sc - mx) : 0.f;
    float sm = e;
    #pragma unroll
    for (int o=16;o;o>>=1) sm += __shfl_xor_sync(0xffffffffu, sm, o);
    float attn = e / sm;
    float a0=0.f, a1=0.f;
    #pragma unroll
    for (int d=0;d<DD;d++){
        float ad = __shfl_sync(0xffffffffu, attn, d);
        int  cd = __shfl_sync(0xffffffffu, c, d);
        const float* hr = g_H + (size_t)cd*FF;
        a0 += ad * hr[lane];
        a1 += ad * hr[lane + 32];
    }
    g_agg[node*FF + lane]      = a0;
    g_agg[node*FF + lane + 32] = a1;
}

// ---------------- 4. per-class GRU: S = GRU(agg+enc, S) -------------------------
// 128 rows/block, 512 threads: 4 per row, 2 f-chunks each. f32x2 FMA.
#define GRU_SMEM ((2*64*192 + 2*128*64) * (int)sizeof(float))
__global__ void __launch_bounds__(512, 1) k_gru(const float* __restrict__ Wx,
                                                const float* __restrict__ Wh,
                                                const float* __restrict__ bvec){
    extern __shared__ float sh[];
    float* Wxs = sh;                   // 64*192
    float* Whs = sh + 64*192;
    float* ms  = sh + 2*64*192;        // 128*64 swizzled
    float* ss  = ms + 128*64;
    int t = threadIdx.x;
    size_t base = (size_t)blockIdx.x * 128;
    {                                   // independent prologue: 96KB weight staging
        const float4* wx4 = (const float4*)Wx;
        const float4* wh4 = (const float4*)Wh;
        float4* wxs4 = (float4*)Wxs;
        float4* whs4 = (float4*)Whs;
        for (int i=t;i<64*192/4;i+=512){ wxs4[i]=wx4[i]; whs4[i]=wh4[i]; }
    }
    pdl_wait();                         // g_agg (attnagg) must be complete
    for (int i=t;i<128*64;i+=512){
        int row = i>>6, k = i&63;
        size_t gr = base + row;
        int sw = (row<<6) | (k ^ (row&31));
        float mv = 0.f;
        if (gr < BV) mv = g_agg[gr*FF+k] + g_enc[gr*FF+k];
        ms[sw] = mv;
        ss[sw] = g_S[gr*FF + k];
    }
    __syncthreads();
    pdl_trigger();
    int row = t & 127, quarter = t >> 7;
    if (base + row >= NC) return;
    const float* mrow = ms + (row<<6);
    const float* srow = ss + (row<<6);
    int c = row & 31;
    size_t orow = (base + row) * FF;
    #pragma unroll
    for (int fo=0; fo<2; fo++){
        int f = (quarter*2 + fo)*8;
        ull X0[4],X1[4],X2[4],H0[4],H1[4],H2[4];
        #pragma unroll
        for (int j=0;j<4;j++){X0[j]=0ull;X1[j]=0ull;X2[j]=0ull;H0[j]=0ull;H1[j]=0ull;H2[j]=0ull;}
        #pragma unroll 2
        for (int k=0;k<64;k++){
            float mkf = mrow[k ^ c];
            float skf = srow[k ^ c];
            ull mk2 = pack2(mkf, mkf);
            ull sk2 = pack2(skf, skf);
            const float* wxp = Wxs + k*192 + f;
            const float* whp = Whs + k*192 + f;
            ulonglong2 xa = ((const ulonglong2*)(wxp))[0];
            ulonglong2 xa2= ((const ulonglong2*)(wxp+4))[0];
            ulonglong2 xb = ((const ulonglong2*)(wxp+64))[0];
            ulonglong2 xb2= ((const ulonglong2*)(wxp+68))[0];
            ulonglong2 xc = ((const ulonglong2*)(wxp+128))[0];
            ulonglong2 xc2= ((const ulonglong2*)(wxp+132))[0];
            ulonglong2 ha = ((const ulonglong2*)(whp))[0];
            ulonglong2 ha2= ((const ulonglong2*)(whp+4))[0];
            ulonglong2 hb = ((const ulonglong2*)(whp+64))[0];
            ulonglong2 hb2= ((const ulonglong2*)(whp+68))[0];
            ulonglong2 hc = ((const ulonglong2*)(whp+128))[0];
            ulonglong2 hc2= ((const ulonglong2*)(whp+132))[0];
            fma2(X0[0], xa.x, mk2);  fma2(X0[1], xa.y, mk2);
            fma2(X0[2], xa2.x, mk2); fma2(X0[3], xa2.y, mk2);
            fma2(X1[0], xb.x, mk2);  fma2(X1[1], xb.y, mk2);
            fma2(X1[2], xb2.x, mk2); fma2(X1[3], xb2.y, mk2);
            fma2(X2[0], xc.x, mk2);  fma2(X2[1], xc.y, mk2);
            fma2(X2[2], xc2.x, mk2); fma2(X2[3], xc2.y, mk2);
            fma2(H0[0], ha.x, sk2);  fma2(H0[1], ha.y, sk2);
            fma2(H0[2], ha2.x, sk2); fma2(H0[3], ha2.y, sk2);
            fma2(H1[0], hb.x, sk2);  fma2(H1[1], hb.y, sk2);
            fma2(H1[2], hb2.x, sk2); fma2(H1[3], hb2.y, sk2);
            fma2(H2[0], hc.x, sk2);  fma2(H2[1], hc.y, sk2);
            fma2(H2[2], hc2.x, sk2); fma2(H2[3], hc2.y, sk2);
        }
        float bz[8], br8[8], bh[8], o[8];
        *(float4*)&bz[0]  = __ldg((const float4*)(bvec+f));
        *(float4*)&bz[4]  = __ldg((const float4*)(bvec+f+4));
        *(float4*)&br8[0] = __ldg((const float4*)(bvec+64+f));
        *(float4*)&br8[4] = __ldg((const float4*)(bvec+64+f+4));
        *(float4*)&bh[0]  = __ldg((const float4*)(bvec+128+f));
        *(float4*)&bh[4]  = __ldg((const float4*)(bvec+128+f+4));
        #pragma unroll
        for (int j=0;j<4;j++){
            float x0a,x0b,x1a,x1b,x2a,x2b,h0a,h0b,h1a,h1b,h2a,h2b;
            unpack2(X0[j],x0a,x0b); unpack2(X1[j],x1a,x1b); unpack2(X2[j],x2a,x2b);
            unpack2(H0[j],h0a,h0b); unpack2(H1[j],h1a,h1b); unpack2(H2[j],h2a,h2b);
            {
                float z    = 1.f/(1.f + __expf(-(x0a + bz[2*j]  + h0a)));
                float r    = 1.f/(1.f + __expf(-(x1a + br8[2*j] + h1a)));
                float cand = tanhf(x2a + bh[2*j] + r*h2a);
                float sold = srow[(f+2*j) ^ c];
                o[2*j] = z*sold + (1.f - z)*cand;
            }
            {
                float z    = 1.f/(1.f + __expf(-(x0b + bz[2*j+1]  + h0b)));
                float r    = 1.f/(1.f + __expf(-(x1b + br8[2*j+1] + h1b)));
                float cand = tanhf(x2b + bh[2*j+1] + r*h2b);
                float sold = srow[(f+2*j+1) ^ c];
                o[2*j+1] = z*sold + (1.f - z)*cand;
            }
        }
        *(float4*)(g_S + orow + f)     = *(float4*)&o[0];
        *(float4*)(g_S + orow + f + 4) = *(float4*)&o[4];
    }
}

// ---------------- 5. 64->32->1 MLP head -------------------------------------------
__global__ void k_mlp(int mode, const float* __restrict__ W1, const float* __restrict__ b1,
                      const float* __restrict__ W2, const float* __restrict__ b2){
    __shared__ float S[128*65];
    __shared__ float W1s[64*32];
    __shared__ float b1s[32], W2s[32];
    const float* in = mode ? g_ns : g_S;
    float* out      = mode ? g_dualvars : g_nwc;
    int nrows       = mode ? BV : NC;
    int t = threadIdx.x;
    int base = blockIdx.x*128;
    for (int i=t;i<2048;i+=128) W1s[i] = W1[i];
    if (t < 32){ b1s[t] = b1[t]; W2s[t] = W2[t]; }
    pdl_wait();
    pdl_trigger();
    for (int c=0;c<64;c++){
        int lin = c*128 + t;
        int r = lin >> 6, k = lin & 63;
        S[r*65 + k] = in[(size_t)base*FF + lin];
    }
    __syncthreads();
    if (base + t >= nrows) return;
    float acc[32];
    #pragma unroll
    for (int h=0;h<32;h++) acc[h] = b1s[h];
    const float* myrow = S + t*65;
    for (int k=0;k<64;k++){
        float s = myrow[k];
        #pragma unroll
        for (int h=0;h<32;h++) acc[h] += s*W1s[k*32+h];
    }
    float o = b2[0];
    #pragma unroll
    for (int h=0;h<32;h++) o += tanhf(acc[h])*W2s[h];
    out[base + t] = o;
}

// ---------------- 6. incoming-gather softmax (expand fused) -----------------------
__global__ void k_inattn(const int* __restrict__ in_idx, const int* __restrict__ inv_adj,
                         const int* __restrict__ adj, const int* __restrict__ num_nodes){
    int lane = threadIdx.x & 31;
    int node = blockIdx.x*8 + (threadIdx.x >> 5);
    int b = node >> 11;
    int nn = num_nodes[b];
    int a2 = 0, ia = 0;
    if (lane < DD){
        int idx = in_idx[node*DD + lane];
        a2 = adj[b*VD + idx];
        ia = inv_adj[node*DD + lane];
    }
    pdl_trigger();
    pdl_wait();
    float sc = -1e30f;
    if (lane < DD){
        float inc = g_nwc[(a2==nn) ? BV : ((b<<11)+a2)];
        sc = inc - ((ia == nn) ? BIGC : 0.f);
    }
    float mx = sc;
    #pragma unroll
    for (int o=16;o;o>>=1) mx = fmaxf(mx, __shfl_xor_sync(0xffffffffu, mx, o));
    float e = (lane < DD) ? __expf(sc - mx) : 0.f;
    float sm = e;
    #pragma unroll
    for (int o=16;o;o>>=1) sm += __shfl_xor_sync(0xffffffffu, sm, o);
    if (lane < DD) g_attnin[node*DD + lane] = e / sm;
}

// ---------------- 7. rev-gather + masked softmax -> normalized ---------------------
__global__ void k_revnorm(const int* __restrict__ rev_idx, const int* __restrict__ adj,
                          const int* __restrict__ num_nodes){
    int lane = threadIdx.x & 31;
    int node = blockIdx.x*8 + (threadIdx.x >> 5);
    int b = node >> 11;
    int ridx = 0, a = 0;
    if (lane < DD){
        ridx = rev_idx[node*DD + lane];
        a = adj[node*DD + lane];
    }
    pdl_trigger();
    pdl_wait();
    float sc = -1e30f;
    if (lane < DD){
        float val = g_attnin[b*VD + ridx];
        sc = val - ((a == num_nodes[b]) ? BIGC : 0.f);
    }
    float mx = sc;
    #pragma unroll
    for (int o=16;o;o>>=1) mx = fmaxf(mx, __shfl_xor_sync(0xffffffffu, mx, o));
    float e = (lane < DD) ? __expf(sc - mx) : 0.f;
    float sm = e;
    #pragma unroll
    for (int o=16;o;o>>=1) sm += __shfl_xor_sync(0xffffffffu, sm, o);
    if (lane < DD) g_norm[node*DD + lane] = e / sm;
}

// ---------------- 8. flow fixed-point on node vector t, 1 block/batch ---------------
#define FLOW_SMEM ((VD + VV + VV + 1024) * (int)sizeof(float))
__global__ void __launch_bounds__(1024) k_flow(const float* __restrict__ demands,
                                               const int* __restrict__ inv_adj,
                                               const int* __restrict__ in_idx,
                                               const int* __restrict__ num_nodes){
    extern __shared__ float sh[];
    float* wT  = sh;              // [DD][VV] transposed weights
    float* ts  = sh + VD;         // VV
    float* sup = ts + VV;         // VV
    float* red = sup + VV;        // 1024
    int b = blockIdx.x, t = threadIdx.x;
    int nn = num_nodes[b];
    int mm[2][DD];
    unsigned mb[2] = {0u, 0u};
    unsigned int sp[2][8];
    float nsq[2];
    // phase 1: inputs only (independent of revnorm)
    #pragma unroll
    for (int n=0;n<2;n++){
        int v = t + n*1024;
        size_t ebase = ((size_t)b*VV + v)*DD;
        int ia[DD];
        #pragma unroll
        for (int d=0;d<DD;d+=4){
            *(int4*)&ia[d]    = __ldg((const int4*)(inv_adj + ebase + d));
            *(int4*)&mm[n][d] = __ldg((const int4*)(in_idx  + ebase + d));
        }
        unsigned bits = 0;
        #pragma unroll
        for (int d=0;d<DD;d++) if (ia[d]==nn) bits |= (1u<<d);
        mb[n] = bits;
        #pragma unroll
        for (int d=0;d<DD;d++){
            int sv = mm[n][d] >> 4;
            if ((d&1)==0) sp[n][d>>1] = (unsigned int)sv;
            else          sp[n][d>>1] |= ((unsigned int)sv) << 16;
        }
        float s = fmaxf(-demands[b*VV + v], 0.f);
        sup[v] = s;
        ts[v] = s;
    }
    pdl_trigger();
    pdl_wait();
    // phase 2: reads of g_norm (revnorm output)
    #pragma unroll
    for (int n=0;n<2;n++){
        int v = t + n*1024;
        float nrm[DD];
        #pragma unroll
        for (int d=0;d<DD;d+=4)
            *(float4*)&nrm[d] = __ldg((const float4*)(g_norm + (size_t)b*VD + v*DD + d));
        float q = 0.f;
        #pragma unroll
        for (int d=0;d<DD;d++) q += nrm[d]*nrm[d];
        nsq[n] = q;
        #pragma unroll
        for (int d=0;d<DD;d++){
            float wv = ((mb[n]>>d)&1u) ? 0.f : g_norm[(size_t)b*VD + mm[n][d]];
            wT[d*VV + v] = wv;
        }
    }
    __syncthreads();
    for (int it=0; it<10; it++){
        float acc[2] = {0.f, 0.f};
        #pragma unroll
        for (int n=0;n<2;n++){
            int v = t + n*1024;
            #pragma unroll
            for (int d=0;d<DD;d++){
                unsigned int pk = sp[n][d>>1];
                int sv = (d&1) ? (pk>>16) : (pk & 0xffff);
                acc[n] += wT[d*VV + v] * ts[sv];
            }
        }
        __syncthreads();
        ts[t]        = sup[t]        + acc[0];
        ts[t + 1024] = sup[t + 1024] + acc[1];
        __syncthreads();
    }
    float c = nsq[0]*ts[t]*ts[t] + nsq[1]*ts[t+1024]*ts[t+1024];
    red[t] = c; __syncthreads();
    for (int s=512; s>0; s>>=1){ if (t < s) red[t] += red[t+s]; __syncthreads(); }
    if (t == 0) g_fc[b] = red[0];
}

// ---------------- 9. node_states = sum over d of class rows -------------------------
__global__ void k_nodestates(const int* __restrict__ adj, const int* __restrict__ num_nodes){
    int lane = threadIdx.x & 31;
    int node = blockIdx.x*8 + (threadIdx.x >> 5);
    int b = node >> 11;
    int nn = num_nodes[b];
    int c = 0;
    if (lane < DD){
        int a = adj[node*DD+lane];
        c = (a==nn) ? BV : ((b<<11)+a);
    }
    float s0=0.f, s1=0.f;
    #pragma unroll
    for (int d=0;d<DD;d++){
        int cd = __shfl_sync(0xffffffffu, c, d);
        const float* sr = g_S + (size_t)cd*FF;
        s0 += sr[lane];
        s1 += sr[lane + 32];
    }
    g_ns[node*FF + lane]      = s0;
    g_ns[node*FF + lane + 32] = s1;
}

// ---------------- 10. dual iterations + quad cost + demand fold ----------------------
__global__ void k_dual(const int* __restrict__ adj, const int* __restrict__ num_nodes,
                       const float* __restrict__ demands){
    __shared__ float red[256];
    int idx = blockIdx.x*256 + threadIdx.x;
    int b = idx >> 15; int node = idx >> 4;
    int a = adj[idx]; int nn = num_nodes[b];
    float mask = (a==nn) ? 1.f : 0.f;
    float valid = 1.f - mask;
    float dv  = g_dualvars[node];
    float dtr = g_dualvars[(b<<11) + a] * valid;
    float dd  = dtr - mask*dv;
    float f = 0.f, ac = 0.f;
    #pragma unroll
    for (int i=0;i<10;i++){
        float g = 2.f*f + dd;
        ac = 0.9f*ac + 0.01f*g;
        f = fmaxf(f - ac, 0.f) * valid;
    }
    float c = f*f + dd*f;
    if ((idx & 15) == 0) c -= dv * demands[node];     // fold dual_demand (once per node)
    red[threadIdx.x] = c; __syncthreads();
    for (int s=128; s>0; s>>=1){ if (threadIdx.x < s) red[threadIdx.x] += red[threadIdx.x+s]; __syncthreads(); }
    if (threadIdx.x == 0) g_dq[blockIdx.x] = red[0];
}

// ---------------- 11. finalize: out[b] = fc - sum(dq partials) ------------------------
__global__ void k_finalize(float* __restrict__ out){
    int w = threadIdx.x >> 5, lane = threadIdx.x & 31;
    if (w < BB){
        float dq = 0.f;
        #pragma unroll
        for (int i=0;i<4;i++) dq += g_dq[w*128 + lane + 32*i];
        #pragma unroll
        for (int o=16;o;o>>=1) dq += __shfl_xor_sync(0xffffffffu, dq, o);
        if (lane == 0) out[w] = g_fc[w] - dq;
    }
}

// ---------------- PDL launch helper -----------------------------------------------
static inline void launch_pdl(const void* fn, int grid, int block, size_t smem, void** args){
    cudaLaunchConfig_t cfg = {};
    cfg.gridDim = dim3((unsigned)grid, 1, 1);
    cfg.blockDim = dim3((unsigned)block, 1, 1);
    cfg.dynamicSmemBytes = smem;
    cfg.stream = 0;
    cudaLaunchAttribute at[1];
    at[0].id = cudaLaunchAttributeProgrammaticStreamSerialization;
    at[0].val.programmaticStreamSerializationAllowed = 1;
    cfg.attrs = at;
    cfg.numAttrs = 1;
    cudaLaunchKernelExC(&cfg, fn, args);
}

// ---------------- launcher -------------------------------------------------------------
extern "C" void kernel_launch(void* const* d_in, const int* in_sizes, int n_in,
                              void* d_out, int out_size){
    const float* node_features = (const float*)d_in[0];
    const float* demands       = (const float*)d_in[1];
    const float* emb           = (const float*)d_in[2];
    const float* enc_W         = (const float*)d_in[3];
    const float* enc_b         = (const float*)d_in[4];
    const float* gat_W         = (const float*)d_in[5];
    const float* gat_b         = (const float*)d_in[6];
    const float* gat_a         = (const float*)d_in[7];
    const float* gru_Wx        = (const float*)d_in[8];
    const float* gru_Wh        = (const float*)d_in[9];
    const float* gru_b         = (const float*)d_in[10];
    const float* dec_W1        = (const float*)d_in[11];
    const float* dec_b1        = (const float*)d_in[12];
    const float* dec_W2        = (const float*)d_in[13];
    const float* dec_b2        = (const float*)d_in[14];
    const float* dual_W1       = (const float*)d_in[15];
    const float* dual_b1       = (const float*)d_in[16];
    const float* dual_W2       = (const float*)d_in[17];
    const float* dual_b2       = (const float*)d_in[18];
    const int*   adj           = (const int*)d_in[19];
    const int*   inv_adj       = (const int*)d_in[20];
    const int*   in_idx        = (const int*)d_in[21];
    const int*   rev_idx       = (const int*)d_in[22];
    const int*   num_nodes     = (const int*)d_in[23];
    float* out = (float*)d_out;

    static cudaStream_t s2 = 0;
    static cudaEvent_t evFork = 0, evJoin = 0;
    if (!s2){
        cudaStreamCreateWithFlags(&s2, cudaStreamNonBlocking);
        cudaEventCreateWithFlags(&evFork, cudaEventDisableTiming);
        cudaEventCreateWithFlags(&evJoin, cudaEventDisableTiming);
    }

    cudaFuncSetAttribute(k_gru,  cudaFuncAttributeMaxDynamicSharedMemorySize, GRU_SMEM);
    cudaFuncSetAttribute(k_gat,  cudaFuncAttributeMaxDynamicSharedMemorySize, GAT_SMEM);
    cudaFuncSetAttribute(k_flow, cudaFuncAttributeMaxDynamicSharedMemorySize, FLOW_SMEM);

    k_enc<<<BV/4 + 16, 256>>>(node_features, emb, enc_W, enc_b);

    for (int l=0; l<2; l++){
        { void* a[] = {(void*)&gat_W, (void*)&gat_b, (void*)&gat_a};
          launch_pdl((const void*)k_gat, NCPAD/128, 512, GAT_SMEM, a); }
        { void* a[] = {(void*)&adj, (void*)&num_nodes};
          launch_pdl((const void*)k_attnagg, BV/8, 256, 0, a); }
        { void* a[] = {(void*)&gru_Wx, (void*)&gru_Wh, (void*)&gru_b};
          launch_pdl((const void*)k_gru, NCPAD/128, 512, GRU_SMEM, a); }
    }

    // decoder MLP (flow head) with PDL on gru2
    int mode0 = 0;
    { void* a[] = {(void*)&mode0, (void*)&dec_W1, (void*)&dec_b1, (void*)&dec_W2, (void*)&dec_b2};
      launch_pdl((const void*)k_mlp, (NC+127)/128, 128, 0, a); }

    // fork: dual branch runs concurrently with the rest of the flow branch
    cudaEventRecord(evFork, 0);
    cudaStreamWaitEvent(s2, evFork, 0);
    k_nodestates<<<BV/8, 256, 0, s2>>>(adj, num_nodes);
    k_mlp<<<BV/128, 128, 0, s2>>>(1, dual_W1, dual_b1, dual_W2, dual_b2);
    k_dual<<<BVD/256, 256, 0, s2>>>(adj, num_nodes, demands);
    cudaEventRecord(evJoin, s2);

    // flow branch tail (main stream) — note: k_inattn's stream predecessor is the
    // event-record node, so launch it normally; PDL resumes from revnorm.
    k_inattn<<<BV/8, 256>>>(in_idx, inv_adj, adj, num_nodes);
    { void* a[] = {(void*)&rev_idx, (void*)&adj, (void*)&num_nodes};
      launch_pdl((const void*)k_revnorm, BV/8, 256, 0, a); }
    { void* a[] = {(void*)&demands, (void*)&inv_adj, (void*)&in_idx, (void*)&num_nodes};
      launch_pdl((const void*)k_flow, BB, 1024, FLOW_SMEM, a); }

    // join, then finalize
    cudaStreamWaitEvent(0, evJoin, 0);
    k_finalize<<<1, 256>>>(out);
}

// round 14
// speedup vs baseline: 1.0744x; 1.0744x over previous
#include <cuda_runtime.h>
#include <math.h>

#define BB 8
#define VV 2048
#define DD 16
#define FF 64
#define EMBD 32
#define HID 32
#define FEAT 16
#define BV (BB*VV)            // 16384
#define BVD (BV*DD)           // 262144
#define VD (VV*DD)            // 32768
#define NC (BV+1)             // 16385 classes (+1 global masked class)
#define NCPAD (65*256)        // 16640
#define NBLK ((NC+127)/128)   // 129 live blocks for gat/gru
#define BIGC 1e9f

typedef unsigned long long ull;

// ---------------- packed f32x2 helpers ----------------------------------------
__device__ __forceinline__ ull pack2(float lo, float hi){
    ull r;
    asm("mov.b64 %0, {%1, %2};" : "=l"(r) : "f"(lo), "f"(hi));
    return r;
}
__device__ __forceinline__ void unpack2(ull v, float& lo, float& hi){
    asm("mov.b64 {%0, %1}, %2;" : "=f"(lo), "=f"(hi) : "l"(v));
}
__device__ __forceinline__ void fma2(ull& d, ull a, ull b){
    asm("fma.rn.f32x2 %0, %1, %2, %0;" : "+l"(d) : "l"(a), "l"(b));
}

// ---------------- scratch (device globals) -----------------------------------
__device__ float g_enc[BV*FF];
__device__ float g_S[NCPAD*FF];      // per-class state
__device__ float g_H[NCPAD*FF];      // per-class tanh(state@W+b)
__device__ float g_sc[NCPAD];        // per-class gat score
__device__ float g_agg[BV*FF];       // per-node agg
__device__ float g_nwc[NCPAD];       // per-class decoder output
__device__ float g_attnin[BVD];
__device__ float g_norm[BVD];
__device__ float g_ns[BV*FF];
__device__ float g_dualvars[BV];
__device__ float g_fc[BB];
__device__ float g_dq[BVD/256];

// ---------------- 1. fused emb-normalize + encoder + S init -------------------
__global__ void k_enc(const float* __restrict__ nf, const float* __restrict__ emb,
                      const float* __restrict__ W, const float* __restrict__ bvec){
    if (blockIdx.x >= BV/4){
        int i = (blockIdx.x - BV/4)*256 + threadIdx.x;     // float4 units, 4096 total
        ((float4*)(g_S + (size_t)BV*FF))[i] = make_float4(0.f,0.f,0.f,0.f);
        return;
    }
    __shared__ float sEmb[4*EMBD];
    int t = threadIdx.x;
    int w = t >> 5, lane = t & 31;
    if (w < 4){
        int v = (blockIdx.x*4 + w) & (VV-1);
        float x = emb[v*EMBD + lane];
        float s = x*x;
        #pragma unroll
        for (int o=16;o;o>>=1) s += __shfl_xor_sync(0xffffffffu, s, o);
        float nrm = sqrtf(s);
        float scale = fminf(1.0f, 1.0f / fmaxf(nrm, 1e-12f));
        sEmb[w*EMBD + lane] = x*scale;
    }
    __syncthreads();
    int nl = t >> 6, f = t & 63;
    int node = blockIdx.x*4 + nl;
    float acc = bvec[f];
    const float* ev = sEmb + nl*EMBD;
    const float* nr = nf + node*FEAT;
    #pragma unroll
    for (int k=0;k<EMBD;k++) acc += ev[k]*W[k*FF+f];
    #pragma unroll
    for (int k=0;k<FEAT;k++) acc += nr[k]*W[(EMBD+k)*FF+f];
    g_enc[node*FF+f] = acc;
    g_S[(size_t)node*FF+f] = acc;
}

// ---------------- 2. per-class GAT: H = tanh(S@W+b), sc = H.a ------------------
// 128 rows/block, 512 threads: 4 threads per row, each 2 f-chunks of 8.
#define GAT_SMEM ((64*64 + 128*64) * (int)sizeof(float))
__global__ void __launch_bounds__(512) k_gat(const float* __restrict__ W,
                                             const float* __restrict__ bvec,
                                             const float* __restrict__ gat_a){
    extern __shared__ float sh[];
    float* Ws   = sh;                 // 64*64
    float* tile = sh + 64*64;         // 128*64 swizzled
    __shared__ float scpart[512];
    int t = threadIdx.x;
    size_t base = (size_t)blockIdx.x * 128;
    for (int i=t;i<64*64;i+=512) Ws[i] = W[i];
    for (int i=t;i<128*64;i+=512){
        int row = i>>6, k = i&63;
        tile[(row<<6) | (k ^ (row&31))] = g_S[base*FF + i];
    }
    __syncthreads();
    int row = t & 127, quarter = t >> 7;
    const float* srow = tile + (row<<6);
    int c = row & 31;
    size_t orow = (base + row) * FF;
    bool live = (base + row) < NC;
    float sc = 0.f;
    #pragma unroll
    for (int fo=0; fo<2; fo++){
        int f = (quarter*2 + fo)*8;
        ull acc[4];
        {
            float b8[8];
            *(float4*)&b8[0] = __ldg((const float4*)(bvec+f));
            *(float4*)&b8[4] = __ldg((const float4*)(bvec+f+4));
            #pragma unroll
            for (int j=0;j<4;j++) acc[j] = pack2(b8[2*j], b8[2*j+1]);
        }
        #pragma unroll 4
        for (int k=0;k<64;k++){
            float skf = srow[k ^ c];
            ull sk2 = pack2(skf, skf);
            const ulonglong2* wp = (const ulonglong2*)(Ws + k*64 + f);
            ulonglong2 w01 = wp[0], w23 = wp[1];
            fma2(acc[0], w01.x, sk2);
            fma2(acc[1], w01.y, sk2);
            fma2(acc[2], w23.x, sk2);
            fma2(acc[3], w23.y, sk2);
        }
        float av[8], hv[8];
        *(float4*)&av[0] = __ldg((const float4*)(gat_a+f));
        *(float4*)&av[4] = __ldg((const float4*)(gat_a+f+4));
        #pragma unroll
        for (int j=0;j<4;j++){
            float a0,a1; unpack2(acc[j], a0, a1);
            hv[2*j]   = tanhf(a0);
            hv[2*j+1] = tanhf(a1);
            sc += hv[2*j]*av[2*j] + hv[2*j+1]*av[2*j+1];
        }
        if (live){
            *(float4*)(g_H + orow + f)     = *(float4*)&hv[0];
            *(float4*)(g_H + orow + f + 4) = *(float4*)&hv[4];
        }
    }
    scpart[t] = sc;
    __syncthreads();
    if (t < 128 && (base + t) < NC)
        g_sc[base + t] = (scpart[t] + scpart[t+128]) + (scpart[t+256] + scpart[t+384]);
}

// ---------------- 3. per-node softmax(D) + agg from class rows ------------------
__global__ void k_attnagg(const int* __restrict__ adj, const int* __restrict__ num_nodes){
    int lane = threadIdx.x & 31;
    int node = blockIdx.x*8 + (threadIdx.x >> 5);
    int b = node >> 11;
    int nn = num_nodes[b];
    int c = 0;
    float sc = -1e30f;
    if (lane < DD){
        int a = adj[node*DD+lane];
        bool m = (a==nn);
        c = m ? BV : ((b<<11)+a);
        sc = g_sc[c] - (m ? BIGC : 0.f);
    }
    float mx = sc;
    #pragma unroll
    for (int o=16;o;o>>=1) mx = fmaxf(mx, __shfl_xor_sync(0xffffffffu, mx, o));
    float e = (lane < DD) ? __expf(sc - mx) : 0.f;
    float sm = e;
    #pragma unroll
    for (int o=16;o;o>>=1) sm += __shfl_xor_sync(0xffffffffu, sm, o);
    float attn = e / sm;
    float a0=0.f, a1=0.f;
    #pragma unroll
    for (int d=0;d<DD;d++){
        float ad = __shfl_sync(0xffffffffu, attn, d);
        int  cd = __shfl_sync(0xffffffffu, c, d);
        const float* hr = g_H + (size_t)cd*FF;
        a0 += ad * hr[lane];
        a1 += ad * hr[lane + 32];
    }
    g_agg[node*FF + lane]      = a0;
    g_agg[node*FF + lane + 32] = a1;
}

// ---------------- 4. per-class GRU: S = GRU(agg+enc, S) -------------------------
// 128 rows/block, 512 threads: 4 per row, 2 f-chunks each. f32x2 FMA.
#define GRU_SMEM ((2*64*192 + 2*128*64) * (int)sizeof(float))
__global__ void __launch_bounds__(512, 1) k_gru(const float* __restrict__ Wx,
                                                const float* __restrict__ Wh,
                                                const float* __restrict__ bvec){
    extern __shared__ float sh[];
    float* Wxs = sh;                   // 64*192
    float* Whs = sh + 64*192;
    float* ms  = sh + 2*64*192;        // 128*64 swizzled
    float* ss  = ms + 128*64;
    int t = threadIdx.x;
    size_t base = (size_t)blockIdx.x * 128;
    {
        const float4* wx4 = (const float4*)Wx;
        const float4* wh4 = (const float4*)Wh;
        float4* wxs4 = (float4*)Wxs;
        float4* whs4 = (float4*)Whs;
        for (int i=t;i<64*192/4;i+=512){ wxs4[i]=wx4[i]; whs4[i]=wh4[i]; }
    }
    for (int i=t;i<128*64;i+=512){
        int row = i>>6, k = i&63;
        size_t gr = base + row;
        int sw = (row<<6) | (k ^ (row&31));
        float mv = 0.f;
        if (gr < BV) mv = g_agg[gr*FF+k] + g_enc[gr*FF+k];
        ms[sw] = mv;
        ss[sw] = g_S[gr*FF + k];
    }
    __syncthreads();
    int row = t & 127, quarter = t >> 7;
    if (base + row >= NC) return;
    const float* mrow = ms + (row<<6);
    const float* srow = ss + (row<<6);
    int c = row & 31;
    size_t orow = (base + row) * FF;
    #pragma unroll
    for (int fo=0; fo<2; fo++){
        int f = (quarter*2 + fo)*8;
        ull X0[4],X1[4],X2[4],H0[4],H1[4],H2[4];
        #pragma unroll
        for (int j=0;j<4;j++){X0[j]=0ull;X1[j]=0ull;X2[j]=0ull;H0[j]=0ull;H1[j]=0ull;H2[j]=0ull;}
        #pragma unroll 2
        for (int k=0;k<64;k++){
            float mkf = mrow[k ^ c];
            float skf = srow[k ^ c];
            ull mk2 = pack2(mkf, mkf);
            ull sk2 = pack2(skf, skf);
            const float* wxp = Wxs + k*192 + f;
            const float* whp = Whs + k*192 + f;
            ulonglong2 xa = ((const ulonglong2*)(wxp))[0];
            ulonglong2 xa2= ((const ulonglong2*)(wxp+4))[0];
            ulonglong2 xb = ((const ulonglong2*)(wxp+64))[0];
            ulonglong2 xb2= ((const ulonglong2*)(wxp+68))[0];
            ulonglong2 xc = ((const ulonglong2*)(wxp+128))[0];
            ulonglong2 xc2= ((const ulonglong2*)(wxp+132))[0];
            ulonglong2 ha = ((const ulonglong2*)(whp))[0];
            ulonglong2 ha2= ((const ulonglong2*)(whp+4))[0];
            ulonglong2 hb = ((const ulonglong2*)(whp+64))[0];
            ulonglong2 hb2= ((const ulonglong2*)(whp+68))[0];
            ulonglong2 hc = ((const ulonglong2*)(whp+128))[0];
            ulonglong2 hc2= ((const ulonglong2*)(whp+132))[0];
            fma2(X0[0], xa.x, mk2);  fma2(X0[1], xa.y, mk2);
            fma2(X0[2], xa2.x, mk2); fma2(X0[3], xa2.y, mk2);
            fma2(X1[0], xb.x, mk2);  fma2(X1[1], xb.y, mk2);
            fma2(X1[2], xb2.x, mk2); fma2(X1[3], xb2.y, mk2);
            fma2(X2[0], xc.x, mk2);  fma2(X2[1], xc.y, mk2);
            fma2(X2[2], xc2.x, mk2); fma2(X2[3], xc2.y, mk2);
            fma2(H0[0], ha.x, sk2);  fma2(H0[1], ha.y, sk2);
            fma2(H0[2], ha2.x, sk2); fma2(H0[3], ha2.y, sk2);
            fma2(H1[0], hb.x, sk2);  fma2(H1[1], hb.y, sk2);
            fma2(H1[2], hb2.x, sk2); fma2(H1[3], hb2.y, sk2);
            fma2(H2[0], hc.x, sk2);  fma2(H2[1], hc.y, sk2);
            fma2(H2[2], hc2.x, sk2); fma2(H2[3], hc2.y, sk2);
        }
        float bz[8], br8[8], bh[8], o[8];
        *(float4*)&bz[0]  = __ldg((const float4*)(bvec+f));
        *(float4*)&bz[4]  = __ldg((const float4*)(bvec+f+4));
        *(float4*)&br8[0] = __ldg((const float4*)(bvec+64+f));
        *(float4*)&br8[4] = __ldg((const float4*)(bvec+64+f+4));
        *(float4*)&bh[0]  = __ldg((const float4*)(bvec+128+f));
        *(float4*)&bh[4]  = __ldg((const float4*)(bvec+128+f+4));
        #pragma unroll
        for (int j=0;j<4;j++){
            float x0a,x0b,x1a,x1b,x2a,x2b,h0a,h0b,h1a,h1b,h2a,h2b;
            unpack2(X0[j],x0a,x0b); unpack2(X1[j],x1a,x1b); unpack2(X2[j],x2a,x2b);
            unpack2(H0[j],h0a,h0b); unpack2(H1[j],h1a,h1b); unpack2(H2[j],h2a,h2b);
            {
                float z    = 1.f/(1.f + __expf(-(x0a + bz[2*j]  + h0a)));
                float r    = 1.f/(1.f + __expf(-(x1a + br8[2*j] + h1a)));
                float cand = tanhf(x2a + bh[2*j] + r*h2a);
                float sold = srow[(f+2*j) ^ c];
                o[2*j] = z*sold + (1.f - z)*cand;
            }
            {
                float z    = 1.f/(1.f + __expf(-(x0b + bz[2*j+1]  + h0b)));
                float r    = 1.f/(1.f + __expf(-(x1b + br8[2*j+1] + h1b)));
                float cand = tanhf(x2b + bh[2*j+1] + r*h2b);
                float sold = srow[(f+2*j+1) ^ c];
                o[2*j+1] = z*sold + (1.f - z)*cand;
            }
        }
        *(float4*)(g_S + orow + f)     = *(float4*)&o[0];
        *(float4*)(g_S + orow + f + 4) = *(float4*)&o[4];
    }
}

// ---------------- 5. 64->32->1 MLP head -------------------------------------------
__global__ void k_mlp(int mode, const float* __restrict__ W1, const float* __restrict__ b1,
                      const float* __restrict__ W2, const float* __restrict__ b2){
    __shared__ float S[128*65];
    __shared__ float W1s[64*32];
    __shared__ float b1s[32], W2s[32];
    const float* in = mode ? g_ns : g_S;
    float* out      = mode ? g_dualvars : g_nwc;
    int nrows       = mode ? BV : NC;
    int t = threadIdx.x;
    int base = blockIdx.x*128;
    for (int i=t;i<2048;i+=128) W1s[i] = W1[i];
    if (t < 32){ b1s[t] = b1[t]; W2s[t] = W2[t]; }
    for (int c=0;c<64;c++){
        int lin = c*128 + t;
        int r = lin >> 6, k = lin & 63;
        S[r*65 + k] = in[(size_t)base*FF + lin];
    }
    __syncthreads();
    if (base + t >= nrows) return;
    float acc[32];
    #pragma unroll
    for (int h=0;h<32;h++) acc[h] = b1s[h];
    const float* myrow = S + t*65;
    for (int k=0;k<64;k++){
        float s = myrow[k];
        #pragma unroll
        for (int h=0;h<32;h++) acc[h] += s*W1s[k*32+h];
    }
    float o = b2[0];
    #pragma unroll
    for (int h=0;h<32;h++) o += tanhf(acc[h])*W2s[h];
    out[base + t] = o;
}

// ---------------- 6. incoming-gather softmax (expand fused) -----------------------
__global__ void k_inattn(const int* __restrict__ in_idx, const int* __restrict__ inv_adj,
                         const int* __restrict__ adj, const int* __restrict__ num_nodes){
    int lane = threadIdx.x & 31;
    int node = blockIdx.x*8 + (threadIdx.x >> 5);
    int b = node >> 11;
    int nn = num_nodes[b];
    float sc = -1e30f;
    if (lane < DD){
        int idx = in_idx[node*DD + lane];
        int a2 = adj[b*VD + idx];
        float inc = g_nwc[(a2==nn) ? BV : ((b<<11)+a2)];
        int ia = inv_adj[node*DD + lane];
        sc = inc - ((ia == nn) ? BIGC : 0.f);
    }
    float mx = sc;
    #pragma unroll
    for (int o=16;o;o>>=1) mx = fmaxf(mx, __shfl_xor_sync(0xffffffffu, mx, o));
    float e = (lane < DD) ? __expf(sc - mx) : 0.f;
    float sm = e;
    #pragma unroll
    for (int o=16;o;o>>=1) sm += __shfl_xor_sync(0xffffffffu, sm, o);
    if (lane < DD) g_attnin[node*DD + lane] = e / sm;
}

// ---------------- 7. rev-gather + masked softmax -> normalized ---------------------
__global__ void k_revnorm(const int* __restrict__ rev_idx, const int* __restrict__ adj,
                          const int* __restrict__ num_nodes){
    int lane = threadIdx.x & 31;
    int node = blockIdx.x*8 + (threadIdx.x >> 5);
    int b = node >> 11;
    float sc = -1e30f;
    if (lane < DD){
        int ridx = rev_idx[node*DD + lane];
        float val = g_attnin[b*VD + ridx];
        int a = adj[node*DD + lane];
        sc = val - ((a == num_nodes[b]) ? BIGC : 0.f);
    }
    float mx = sc;
    #pragma unroll
    for (int o=16;o;o>>=1) mx = fmaxf(mx, __shfl_xor_sync(0xffffffffu, mx, o));
    float e = (lane < DD) ? __expf(sc - mx) : 0.f;
    float sm = e;
    #pragma unroll
    for (int o=16;o;o>>=1) sm += __shfl_xor_sync(0xffffffffu, sm, o);
    if (lane < DD) g_norm[node*DD + lane] = e / sm;
}

// ---------------- 8. flow fixed-point on node vector t, 1 block/batch ---------------
#define FLOW_SMEM ((VD + VV + VV + 1024) * (int)sizeof(float))
__global__ void __launch_bounds__(1024) k_flow(const float* __restrict__ demands,
                                               const int* __restrict__ inv_adj,
                                               const int* __restrict__ in_idx,
                                               const int* __restrict__ num_nodes){
    extern __shared__ float sh[];
    float* wT  = sh;              // [DD][VV] transposed weights
    float* ts  = sh + VD;         // VV
    float* sup = ts + VV;         // VV
    float* red = sup + VV;        // 1024
    int b = blockIdx.x, t = threadIdx.x;
    int nn = num_nodes[b];
    unsigned int sp[2][8];        // packed source node indices (16-bit)
    float nsq[2];
    #pragma unroll
    for (int n=0;n<2;n++){
        int v = t + n*1024;
        size_t ebase = ((size_t)b*VV + v)*DD;
        int ia[DD], m[DD];
        #pragma unroll
        for (int d=0;d<DD;d+=4){
            *(int4*)&ia[d] = __ldg((const int4*)(inv_adj + ebase + d));
            *(int4*)&m[d]  = __ldg((const int4*)(in_idx  + ebase + d));
        }
        float nrm[DD];
        #pragma unroll
        for (int d=0;d<DD;d+=4)
            *(float4*)&nrm[d] = __ldg((const float4*)(g_norm + (size_t)b*VD + v*DD + d));
        float q = 0.f;
        #pragma unroll
        for (int d=0;d<DD;d++) q += nrm[d]*nrm[d];
        nsq[n] = q;
        #pragma unroll
        for (int d=0;d<DD;d++){
            float wv = (ia[d]==nn) ? 0.f : g_norm[(size_t)b*VD + m[d]];
            wT[d*VV + v] = wv;
            int sv = m[d] >> 4;
            if ((d&1)==0) sp[n][d>>1] = (unsigned int)sv;
            else          sp[n][d>>1] |= ((unsigned int)sv) << 16;
        }
        float s = fmaxf(-demands[b*VV + v], 0.f);
        sup[v] = s;
        ts[v] = s;
    }
    __syncthreads();
    for (int it=0; it<10; it++){
        float acc[2] = {0.f, 0.f};
        #pragma unroll
        for (int n=0;n<2;n++){
            int v = t + n*1024;
            #pragma unroll
            for (int d=0;d<DD;d++){
                unsigned int pk = sp[n][d>>1];
                int sv = (d&1) ? (pk>>16) : (pk & 0xffff);
                acc[n] += wT[d*VV + v] * ts[sv];
            }
        }
        __syncthreads();
        ts[t]        = sup[t]        + acc[0];
        ts[t + 1024] = sup[t + 1024] + acc[1];
        __syncthreads();
    }
    float c = nsq[0]*ts[t]*ts[t] + nsq[1]*ts[t+1024]*ts[t+1024];
    red[t] = c; __syncthreads();
    for (int s=512; s>0; s>>=1){ if (t < s) red[t] += red[t+s]; __syncthreads(); }
    if (t == 0) g_fc[b] = red[0];
}

// ---------------- 9. node_states = sum over d of class rows -------------------------
__global__ void k_nodestates(const int* __restrict__ adj, const int* __restrict__ num_nodes){
    int lane = threadIdx.x & 31;
    int node = blockIdx.x*8 + (threadIdx.x >> 5);
    int b = node >> 11;
    int nn = num_nodes[b];
    int c = 0;
    if (lane < DD){
        int a = adj[node*DD+lane];
        c = (a==nn) ? BV : ((b<<11)+a);
    }
    float s0=0.f, s1=0.f;
    #pragma unroll
    for (int d=0;d<DD;d++){
        int cd = __shfl_sync(0xffffffffu, c, d);
        const float* sr = g_S + (size_t)cd*FF;
        s0 += sr[lane];
        s1 += sr[lane + 32];
    }
    g_ns[node*FF + lane]      = s0;
    g_ns[node*FF + lane + 32] = s1;
}

// ---------------- 10. dual iterations + quad cost + demand fold ----------------------
__global__ void k_dual(const int* __restrict__ adj, const int* __restrict__ num_nodes,
                       const float* __restrict__ demands){
    __shared__ float red[256];
    int idx = blockIdx.x*256 + threadIdx.x;
    int b = idx >> 15; int node = idx >> 4;
    int a = adj[idx]; int nn = num_nodes[b];
    float mask = (a==nn) ? 1.f : 0.f;
    float valid = 1.f - mask;
    float dv  = g_dualvars[node];
    float dtr = g_dualvars[(b<<11) + a] * valid;
    float dd  = dtr - mask*dv;
    float f = 0.f, ac = 0.f;
    #pragma unroll
    for (int i=0;i<10;i++){
        float g = 2.f*f + dd;
        ac = 0.9f*ac + 0.01f*g;
        f = fmaxf(f - ac, 0.f) * valid;
    }
    float c = f*f + dd*f;
    if ((idx & 15) == 0) c -= dv * demands[node];     // fold dual_demand (once per node)
    red[threadIdx.x] = c; __syncthreads();
    for (int s=128; s>0; s>>=1){ if (threadIdx.x < s) red[threadIdx.x] += red[threadIdx.x+s]; __syncthreads(); }
    if (threadIdx.x == 0) g_dq[blockIdx.x] = red[0];
}

// ---------------- 11. finalize: out[b] = fc - sum(dq partials) ------------------------
__global__ void k_finalize(float* __restrict__ out){
    int w = threadIdx.x >> 5, lane = threadIdx.x & 31;
    if (w < BB){
        float dq = 0.f;
        #pragma unroll
        for (int i=0;i<4;i++) dq += g_dq[w*128 + lane + 32*i];
        #pragma unroll
        for (int o=16;o;o>>=1) dq += __shfl_xor_sync(0xffffffffu, dq, o);
        if (lane == 0) out[w] = g_fc[w] - dq;
    }
}

// ---------------- launcher -------------------------------------------------------------
extern "C" void kernel_launch(void* const* d_in, const int* in_sizes, int n_in,
                              void* d_out, int out_size){
    const float* node_features = (const float*)d_in[0];
    const float* demands       = (const float*)d_in[1];
    const float* emb           = (const float*)d_in[2];
    const float* enc_W         = (const float*)d_in[3];
    const float* enc_b         = (const float*)d_in[4];
    const float* gat_W         = (const float*)d_in[5];
    const float* gat_b         = (const float*)d_in[6];
    const float* gat_a         = (const float*)d_in[7];
    const float* gru_Wx        = (const float*)d_in[8];
    const float* gru_Wh        = (const float*)d_in[9];
    const float* gru_b         = (const float*)d_in[10];
    const float* dec_W1        = (const float*)d_in[11];
    const float* dec_b1        = (const float*)d_in[12];
    const float* dec_W2        = (const float*)d_in[13];
    const float* dec_b2        = (const float*)d_in[14];
    const float* dual_W1       = (const float*)d_in[15];
    const float* dual_b1       = (const float*)d_in[16];
    const float* dual_W2       = (const float*)d_in[17];
    const float* dual_b2       = (const float*)d_in[18];
    const int*   adj           = (const int*)d_in[19];
    const int*   inv_adj       = (const int*)d_in[20];
    const int*   in_idx        = (const int*)d_in[21];
    const int*   rev_idx       = (const int*)d_in[22];
    const int*   num_nodes     = (const int*)d_in[23];
    float* out = (float*)d_out;

    // Lazily created once (first call is the non-captured correctness run); no
    // device memory is allocated by streams/events.
    static cudaStream_t s2 = 0;
    static cudaEvent_t evFork = 0, evJoin = 0;
    if (!s2){
        cudaStreamCreateWithFlags(&s2, cudaStreamNonBlocking);
        cudaEventCreateWithFlags(&evFork, cudaEventDisableTiming);
        cudaEventCreateWithFlags(&evJoin, cudaEventDisableTiming);
    }

    cudaFuncSetAttribute(k_gru,  cudaFuncAttributeMaxDynamicSharedMemorySize, GRU_SMEM);
    cudaFuncSetAttribute(k_gat,  cudaFuncAttributeMaxDynamicSharedMemorySize, GAT_SMEM);
    cudaFuncSetAttribute(k_flow, cudaFuncAttributeMaxDynamicSharedMemorySize, FLOW_SMEM);

    k_enc<<<BV/4 + 16, 256>>>(node_features, emb, enc_W, enc_b);

    for (int l=0; l<2; l++){
        k_gat    <<<NBLK, 512, GAT_SMEM>>>(gat_W, gat_b, gat_a);
        k_attnagg<<<BV/8, 256>>>(adj, num_nodes);
        k_gru    <<<NBLK, 512, GRU_SMEM>>>(gru_Wx, gru_Wh, gru_b);
    }

    // fork: dual branch runs concurrently with the flow branch
    cudaEventRecord(evFork, 0);
    cudaStreamWaitEvent(s2, evFork, 0);

    // dual branch (side stream)
    k_nodestates<<<BV/8, 256, 0, s2>>>(adj, num_nodes);
    k_mlp<<<BV/128, 128, 0, s2>>>(1, dual_W1, dual_b1, dual_W2, dual_b2);
    k_dual<<<BVD/256, 256, 0, s2>>>(adj, num_nodes, demands);
    cudaEventRecord(evJoin, s2);

    // flow branch (main stream)
    k_mlp<<<(NC+127)/128, 128>>>(0, dec_W1, dec_b1, dec_W2, dec_b2);
    k_inattn <<<BV/8, 256>>>(in_idx, inv_adj, adj, num_nodes);
    k_revnorm<<<BV/8, 256>>>(rev_idx, adj, num_nodes);
    k_flow<<<BB, 1024, FLOW_SMEM>>>(demands, inv_adj, in_idx, num_nodes);

    // join, then finalize
    cudaStreamWaitEvent(0, evJoin, 0);
    k_finalize<<<1, 256>>>(out);
}

// round 15
// speedup vs baseline: 1.1036x; 1.0272x over previous
#include <cuda_runtime.h>
#include <math.h>

#define BB 8
#define VV 2048
#define DD 16
#define FF 64
#define EMBD 32
#define HID 32
#define FEAT 16
#define BV (BB*VV)            // 16384
#define BVD (BV*DD)           // 262144
#define VD (VV*DD)            // 32768
#define NC (BV+1)             // 16385 classes (+1 global masked class)
#define NCPAD (65*256)        // 16640
#define NBLK ((NC+127)/128)   // 129 live blocks for gat/gru
#define BIGC 1e9f

typedef unsigned long long ull;

// ---------------- packed f32x2 helpers ----------------------------------------
__device__ __forceinline__ ull pack2(float lo, float hi){
    ull r;
    asm("mov.b64 %0, {%1, %2};" : "=l"(r) : "f"(lo), "f"(hi));
    return r;
}
__device__ __forceinline__ void unpack2(ull v, float& lo, float& hi){
    asm("mov.b64 {%0, %1}, %2;" : "=f"(lo), "=f"(hi) : "l"(v));
}
__device__ __forceinline__ void fma2(ull& d, ull a, ull b){
    asm("fma.rn.f32x2 %0, %1, %2, %0;" : "+l"(d) : "l"(a), "l"(b));
}

// ---------------- scratch (device globals) -----------------------------------
__device__ float g_enc[BV*FF];
__device__ float g_S[NCPAD*FF];      // per-class state
__device__ float g_H[NCPAD*FF];      // per-class tanh(state@W+b)
__device__ float g_sc[NCPAD];        // per-class gat score
__device__ float g_agg[BV*FF];       // per-node agg
__device__ float g_nwc[NCPAD];       // per-class decoder output
__device__ float g_attnin[BVD];
__device__ float g_norm[BVD];
__device__ float g_ns[BV*FF];
__device__ float g_dualvars[BV];
__device__ float g_fc[BB];
__device__ float g_dq[BVD/256];

// ---------------- 1. fused emb-normalize + encoder + S init -------------------
__global__ void k_enc(const float* __restrict__ nf, const float* __restrict__ emb,
                      const float* __restrict__ W, const float* __restrict__ bvec){
    if (blockIdx.x >= BV/4){
        int i = (blockIdx.x - BV/4)*256 + threadIdx.x;     // float4 units, 4096 total
        ((float4*)(g_S + (size_t)BV*FF))[i] = make_float4(0.f,0.f,0.f,0.f);
        return;
    }
    __shared__ float sEmb[4*EMBD];
    int t = threadIdx.x;
    int w = t >> 5, lane = t & 31;
    if (w < 4){
        int v = (blockIdx.x*4 + w) & (VV-1);
        float x = emb[v*EMBD + lane];
        float s = x*x;
        #pragma unroll
        for (int o=16;o;o>>=1) s += __shfl_xor_sync(0xffffffffu, s, o);
        float nrm = sqrtf(s);
        float scale = fminf(1.0f, 1.0f / fmaxf(nrm, 1e-12f));
        sEmb[w*EMBD + lane] = x*scale;
    }
    __syncthreads();
    int nl = t >> 6, f = t & 63;
    int node = blockIdx.x*4 + nl;
    float acc = bvec[f];
    const float* ev = sEmb + nl*EMBD;
    const float* nr = nf + node*FEAT;
    #pragma unroll
    for (int k=0;k<EMBD;k++) acc += ev[k]*W[k*FF+f];
    #pragma unroll
    for (int k=0;k<FEAT;k++) acc += nr[k]*W[(EMBD+k)*FF+f];
    g_enc[node*FF+f] = acc;
    g_S[(size_t)node*FF+f] = acc;
}

// ---------------- 2. per-class GAT: H = tanh(S@W+b), sc = H.a ------------------
// 128 rows/block, 512 threads: 4 threads per row, each 2 f-chunks of 8.
#define GAT_SMEM ((64*64 + 128*64) * (int)sizeof(float))
__global__ void __launch_bounds__(512) k_gat(const float* __restrict__ W,
                                             const float* __restrict__ bvec,
                                             const float* __restrict__ gat_a){
    extern __shared__ float sh[];
    float* Ws   = sh;                 // 64*64
    float* tile = sh + 64*64;         // 128*64 swizzled
    __shared__ float scpart[512];
    int t = threadIdx.x;
    size_t base = (size_t)blockIdx.x * 128;
    for (int i=t;i<64*64;i+=512) Ws[i] = W[i];
    for (int i=t;i<128*64;i+=512){
        int row = i>>6, k = i&63;
        tile[(row<<6) | (k ^ (row&31))] = g_S[base*FF + i];
    }
    __syncthreads();
    int row = t & 127, quarter = t >> 7;
    const float* srow = tile + (row<<6);
    int c = row & 31;
    size_t orow = (base + row) * FF;
    bool live = (base + row) < NC;
    float sc = 0.f;
    #pragma unroll
    for (int fo=0; fo<2; fo++){
        int f = (quarter*2 + fo)*8;
        ull acc[4];
        {
            float b8[8];
            *(float4*)&b8[0] = __ldg((const float4*)(bvec+f));
            *(float4*)&b8[4] = __ldg((const float4*)(bvec+f+4));
            #pragma unroll
            for (int j=0;j<4;j++) acc[j] = pack2(b8[2*j], b8[2*j+1]);
        }
        #pragma unroll 4
        for (int k=0;k<64;k++){
            float skf = srow[k ^ c];
            ull sk2 = pack2(skf, skf);
            const ulonglong2* wp = (const ulonglong2*)(Ws + k*64 + f);
            ulonglong2 w01 = wp[0], w23 = wp[1];
            fma2(acc[0], w01.x, sk2);
            fma2(acc[1], w01.y, sk2);
            fma2(acc[2], w23.x, sk2);
            fma2(acc[3], w23.y, sk2);
        }
        float av[8], hv[8];
        *(float4*)&av[0] = __ldg((const float4*)(gat_a+f));
        *(float4*)&av[4] = __ldg((const float4*)(gat_a+f+4));
        #pragma unroll
        for (int j=0;j<4;j++){
            float a0,a1; unpack2(acc[j], a0, a1);
            hv[2*j]   = tanhf(a0);
            hv[2*j+1] = tanhf(a1);
            sc += hv[2*j]*av[2*j] + hv[2*j+1]*av[2*j+1];
        }
        if (live){
            *(float4*)(g_H + orow + f)     = *(float4*)&hv[0];
            *(float4*)(g_H + orow + f + 4) = *(float4*)&hv[4];
        }
    }
    scpart[t] = sc;
    __syncthreads();
    if (t < 128 && (base + t) < NC)
        g_sc[base + t] = (scpart[t] + scpart[t+128]) + (scpart[t+256] + scpart[t+384]);
}

// ---------------- 3. per-node softmax(D) + agg from class rows ------------------
__global__ void k_attnagg(const int* __restrict__ adj, const int* __restrict__ num_nodes){
    int lane = threadIdx.x & 31;
    int node = blockIdx.x*8 + (threadIdx.x >> 5);
    int b = node >> 11;
    int nn = num_nodes[b];
    int c = 0;
    float sc = -1e30f;
    if (lane < DD){
        int a = adj[node*DD+lane];
        bool m = (a==nn);
        c = m ? BV : ((b<<11)+a);
        sc = g_sc[c] - (m ? BIGC : 0.f);
    }
    float mx = sc;
    #pragma unroll
    for (int o=16;o;o>>=1) mx = fmaxf(mx, __shfl_xor_sync(0xffffffffu, mx, o));
    float e = (lane < DD) ? __expf(sc - mx) : 0.f;
    float sm = e;
    #pragma unroll
    for (int o=16;o;o>>=1) sm += __shfl_xor_sync(0xffffffffu, sm, o);
    float attn = e / sm;
    float a0=0.f, a1=0.f;
    #pragma unroll
    for (int d=0;d<DD;d++){
        float ad = __shfl_sync(0xffffffffu, attn, d);
        int  cd = __shfl_sync(0xffffffffu, c, d);
        const float* hr = g_H + (size_t)cd*FF;
        a0 += ad * hr[lane];
        a1 += ad * hr[lane + 32];
    }
    g_agg[node*FF + lane]      = a0;
    g_agg[node*FF + lane + 32] = a1;
}

// ---------------- 4. per-class GRU: S = GRU(agg+enc, S) -------------------------
// 128 rows/block, 512 threads: 4 per row, 2 f-chunks each. f32x2 FMA.
#define GRU_SMEM ((2*64*192 + 2*128*64) * (int)sizeof(float))
__global__ void __launch_bounds__(512, 1) k_gru(const float* __restrict__ Wx,
                                                const float* __restrict__ Wh,
                                                const float* __restrict__ bvec){
    extern __shared__ float sh[];
    float* Wxs = sh;                   // 64*192
    float* Whs = sh + 64*192;
    float* ms  = sh + 2*64*192;        // 128*64 swizzled
    float* ss  = ms + 128*64;
    int t = threadIdx.x;
    size_t base = (size_t)blockIdx.x * 128;
    {
        const float4* wx4 = (const float4*)Wx;
        const float4* wh4 = (const float4*)Wh;
        float4* wxs4 = (float4*)Wxs;
        float4* whs4 = (float4*)Whs;
        for (int i=t;i<64*192/4;i+=512){ wxs4[i]=wx4[i]; whs4[i]=wh4[i]; }
    }
    for (int i=t;i<128*64;i+=512){
        int row = i>>6, k = i&63;
        size_t gr = base + row;
        int sw = (row<<6) | (k ^ (row&31));
        float mv = 0.f;
        if (gr < BV) mv = g_agg[gr*FF+k] + g_enc[gr*FF+k];
        ms[sw] = mv;
        ss[sw] = g_S[gr*FF + k];
    }
    __syncthreads();
    int row = t & 127, quarter = t >> 7;
    if (base + row >= NC) return;
    const float* mrow = ms + (row<<6);
    const float* srow = ss + (row<<6);
    int c = row & 31;
    size_t orow = (base + row) * FF;
    #pragma unroll
    for (int fo=0; fo<2; fo++){
        int f = (quarter*2 + fo)*8;
        ull X0[4],X1[4],X2[4],H0[4],H1[4],H2[4];
        #pragma unroll
        for (int j=0;j<4;j++){X0[j]=0ull;X1[j]=0ull;X2[j]=0ull;H0[j]=0ull;H1[j]=0ull;H2[j]=0ull;}
        #pragma unroll 2
        for (int k=0;k<64;k++){
            float mkf = mrow[k ^ c];
            float skf = srow[k ^ c];
            ull mk2 = pack2(mkf, mkf);
            ull sk2 = pack2(skf, skf);
            const float* wxp = Wxs + k*192 + f;
            const float* whp = Whs + k*192 + f;
            ulonglong2 xa = ((const ulonglong2*)(wxp))[0];
            ulonglong2 xa2= ((const ulonglong2*)(wxp+4))[0];
            ulonglong2 xb = ((const ulonglong2*)(wxp+64))[0];
            ulonglong2 xb2= ((const ulonglong2*)(wxp+68))[0];
            ulonglong2 xc = ((const ulonglong2*)(wxp+128))[0];
            ulonglong2 xc2= ((const ulonglong2*)(wxp+132))[0];
            ulonglong2 ha = ((const ulonglong2*)(whp))[0];
            ulonglong2 ha2= ((const ulonglong2*)(whp+4))[0];
            ulonglong2 hb = ((const ulonglong2*)(whp+64))[0];
            ulonglong2 hb2= ((const ulonglong2*)(whp+68))[0];
            ulonglong2 hc = ((const ulonglong2*)(whp+128))[0];
            ulonglong2 hc2= ((const ulonglong2*)(whp+132))[0];
            fma2(X0[0], xa.x, mk2);  fma2(X0[1], xa.y, mk2);
            fma2(X0[2], xa2.x, mk2); fma2(X0[3], xa2.y, mk2);
            fma2(X1[0], xb.x, mk2);  fma2(X1[1], xb.y, mk2);
            fma2(X1[2], xb2.x, mk2); fma2(X1[3], xb2.y, mk2);
            fma2(X2[0], xc.x, mk2);  fma2(X2[1], xc.y, mk2);
            fma2(X2[2], xc2.x, mk2); fma2(X2[3], xc2.y, mk2);
            fma2(H0[0], ha.x, sk2);  fma2(H0[1], ha.y, sk2);
            fma2(H0[2], ha2.x, sk2); fma2(H0[3], ha2.y, sk2);
            fma2(H1[0], hb.x, sk2);  fma2(H1[1], hb.y, sk2);
            fma2(H1[2], hb2.x, sk2); fma2(H1[3], hb2.y, sk2);
            fma2(H2[0], hc.x, sk2);  fma2(H2[1], hc.y, sk2);
            fma2(H2[2], hc2.x, sk2); fma2(H2[3], hc2.y, sk2);
        }
        float bz[8], br8[8], bh[8], o[8];
        *(float4*)&bz[0]  = __ldg((const float4*)(bvec+f));
        *(float4*)&bz[4]  = __ldg((const float4*)(bvec+f+4));
        *(float4*)&br8[0] = __ldg((const float4*)(bvec+64+f));
        *(float4*)&br8[4] = __ldg((const float4*)(bvec+64+f+4));
        *(float4*)&bh[0]  = __ldg((const float4*)(bvec+128+f));
        *(float4*)&bh[4]  = __ldg((const float4*)(bvec+128+f+4));
        #pragma unroll
        for (int j=0;j<4;j++){
            float x0a,x0b,x1a,x1b,x2a,x2b,h0a,h0b,h1a,h1b,h2a,h2b;
            unpack2(X0[j],x0a,x0b); unpack2(X1[j],x1a,x1b); unpack2(X2[j],x2a,x2b);
            unpack2(H0[j],h0a,h0b); unpack2(H1[j],h1a,h1b); unpack2(H2[j],h2a,h2b);
            {
                float z    = 1.f/(1.f + __expf(-(x0a + bz[2*j]  + h0a)));
                float r    = 1.f/(1.f + __expf(-(x1a + br8[2*j] + h1a)));
                float cand = tanhf(x2a + bh[2*j] + r*h2a);
                float sold = srow[(f+2*j) ^ c];
                o[2*j] = z*sold + (1.f - z)*cand;
            }
            {
                float z    = 1.f/(1.f + __expf(-(x0b + bz[2*j+1]  + h0b)));
                float r    = 1.f/(1.f + __expf(-(x1b + br8[2*j+1] + h1b)));
                float cand = tanhf(x2b + bh[2*j+1] + r*h2b);
                float sold = srow[(f+2*j+1) ^ c];
                o[2*j+1] = z*sold + (1.f - z)*cand;
            }
        }
        *(float4*)(g_S + orow + f)     = *(float4*)&o[0];
        *(float4*)(g_S + orow + f + 4) = *(float4*)&o[4];
    }
}

// ---------------- 5. 64->32->1 MLP head -------------------------------------------
__global__ void k_mlp(int mode, const float* __restrict__ W1, const float* __restrict__ b1,
                      const float* __restrict__ W2, const float* __restrict__ b2){
    __shared__ float S[128*65];
    __shared__ float W1s[64*32];
    __shared__ float b1s[32], W2s[32];
    const float* in = mode ? g_ns : g_S;
    float* out      = mode ? g_dualvars : g_nwc;
    int nrows       = mode ? BV : NC;
    int t = threadIdx.x;
    int base = blockIdx.x*128;
    for (int i=t;i<2048;i+=128) W1s[i] = W1[i];
    if (t < 32){ b1s[t] = b1[t]; W2s[t] = W2[t]; }
    for (int c=0;c<64;c++){
        int lin = c*128 + t;
        int r = lin >> 6, k = lin & 63;
        S[r*65 + k] = in[(size_t)base*FF + lin];
    }
    __syncthreads();
    if (base + t >= nrows) return;
    float acc[32];
    #pragma unroll
    for (int h=0;h<32;h++) acc[h] = b1s[h];
    const float* myrow = S + t*65;
    for (int k=0;k<64;k++){
        float s = myrow[k];
        #pragma unroll
        for (int h=0;h<32;h++) acc[h] += s*W1s[k*32+h];
    }
    float o = b2[0];
    #pragma unroll
    for (int h=0;h<32;h++) o += tanhf(acc[h])*W2s[h];
    out[base + t] = o;
}

// ---------------- 6. incoming-gather softmax (expand fused) -----------------------
__global__ void k_inattn(const int* __restrict__ in_idx, const int* __restrict__ inv_adj,
                         const int* __restrict__ adj, const int* __restrict__ num_nodes){
    int lane = threadIdx.x & 31;
    int node = blockIdx.x*8 + (threadIdx.x >> 5);
    int b = node >> 11;
    int nn = num_nodes[b];
    float sc = -1e30f;
    if (lane < DD){
        int idx = in_idx[node*DD + lane];
        int a2 = adj[b*VD + idx];
        float inc = g_nwc[(a2==nn) ? BV : ((b<<11)+a2)];
        int ia = inv_adj[node*DD + lane];
        sc = inc - ((ia == nn) ? BIGC : 0.f);
    }
    float mx = sc;
    #pragma unroll
    for (int o=16;o;o>>=1) mx = fmaxf(mx, __shfl_xor_sync(0xffffffffu, mx, o));
    float e = (lane < DD) ? __expf(sc - mx) : 0.f;
    float sm = e;
    #pragma unroll
    for (int o=16;o;o>>=1) sm += __shfl_xor_sync(0xffffffffu, sm, o);
    if (lane < DD) g_attnin[node*DD + lane] = e / sm;
}

// ---------------- 7. rev-gather + masked softmax -> normalized ---------------------
__global__ void k_revnorm(const int* __restrict__ rev_idx, const int* __restrict__ adj,
                          const int* __restrict__ num_nodes){
    int lane = threadIdx.x & 31;
    int node = blockIdx.x*8 + (threadIdx.x >> 5);
    int b = node >> 11;
    float sc = -1e30f;
    if (lane < DD){
        int ridx = rev_idx[node*DD + lane];
        float val = g_attnin[b*VD + ridx];
        int a = adj[node*DD + lane];
        sc = val - ((a == num_nodes[b]) ? BIGC : 0.f);
    }
    float mx = sc;
    #pragma unroll
    for (int o=16;o;o>>=1) mx = fmaxf(mx, __shfl_xor_sync(0xffffffffu, mx, o));
    float e = (lane < DD) ? __expf(sc - mx) : 0.f;
    float sm = e;
    #pragma unroll
    for (int o=16;o;o>>=1) sm += __shfl_xor_sync(0xffffffffu, sm, o);
    if (lane < DD) g_norm[node*DD + lane] = e / sm;
}

// ---------------- 8. flow fixed-point, 1 block/batch ---------------------------------
// Weights live in registers (invariant across iterations); double-buffered ts
// halves the barriers (1 per iteration).
#define FLOW_SMEM ((3*VV + 1024) * (int)sizeof(float))
__global__ void __launch_bounds__(1024) k_flow(const float* __restrict__ demands,
                                               const int* __restrict__ inv_adj,
                                               const int* __restrict__ in_idx,
                                               const int* __restrict__ num_nodes){
    extern __shared__ float sh[];
    float* ts0 = sh;              // VV
    float* ts1 = ts0 + VV;        // VV
    float* sup = ts1 + VV;        // VV
    float* red = sup + VV;        // 1024
    int b = blockIdx.x, t = threadIdx.x;
    int nn = num_nodes[b];
    unsigned int sp[2][8];        // packed source node indices (16-bit)
    float wreg[2][DD];            // per-edge weights, register-resident
    float nsq[2], supr[2];
    #pragma unroll
    for (int n=0;n<2;n++){
        int v = t + n*1024;
        size_t ebase = ((size_t)b*VV + v)*DD;
        int ia[DD], m[DD];
        #pragma unroll
        for (int d=0;d<DD;d+=4){
            *(int4*)&ia[d] = __ldg((const int4*)(inv_adj + ebase + d));
            *(int4*)&m[d]  = __ldg((const int4*)(in_idx  + ebase + d));
        }
        float nrm[DD];
        #pragma unroll
        for (int d=0;d<DD;d+=4)
            *(float4*)&nrm[d] = __ldg((const float4*)(g_norm + (size_t)b*VD + v*DD + d));
        float q = 0.f;
        #pragma unroll
        for (int d=0;d<DD;d++) q += nrm[d]*nrm[d];
        nsq[n] = q;
        #pragma unroll
        for (int d=0;d<DD;d++){
            wreg[n][d] = (ia[d]==nn) ? 0.f : g_norm[(size_t)b*VD + m[d]];
            int sv = m[d] >> 4;
            if ((d&1)==0) sp[n][d>>1] = (unsigned int)sv;
            else          sp[n][d>>1] |= ((unsigned int)sv) << 16;
        }
        float s = fmaxf(-demands[b*VV + v], 0.f);
        sup[v] = s;
        supr[n] = s;
        ts0[v] = s;
    }
    __syncthreads();
    float* tsA = ts0;
    float* tsB = ts1;
    for (int it=0; it<10; it++){
        float acc[2] = {0.f, 0.f};
        #pragma unroll
        for (int n=0;n<2;n++){
            #pragma unroll
            for (int d=0;d<DD;d++){
                unsigned int pk = sp[n][d>>1];
                int sv = (d&1) ? (pk>>16) : (pk & 0xffff);
                acc[n] += wreg[n][d] * tsA[sv];
            }
        }
        tsB[t]        = supr[0] + acc[0];
        tsB[t + 1024] = supr[1] + acc[1];
        __syncthreads();
        float* tmp = tsA; tsA = tsB; tsB = tmp;
    }
    float c = nsq[0]*tsA[t]*tsA[t] + nsq[1]*tsA[t+1024]*tsA[t+1024];
    red[t] = c; __syncthreads();
    for (int s=512; s>0; s>>=1){ if (t < s) red[t] += red[t+s]; __syncthreads(); }
    if (t == 0) g_fc[b] = red[0];
}

// ---------------- 9. node_states = sum over d of class rows -------------------------
__global__ void k_nodestates(const int* __restrict__ adj, const int* __restrict__ num_nodes){
    int lane = threadIdx.x & 31;
    int node = blockIdx.x*8 + (threadIdx.x >> 5);
    int b = node >> 11;
    int nn = num_nodes[b];
    int c = 0;
    if (lane < DD){
        int a = adj[node*DD+lane];
        c = (a==nn) ? BV : ((b<<11)+a);
    }
    float s0=0.f, s1=0.f;
    #pragma unroll
    for (int d=0;d<DD;d++){
        int cd = __shfl_sync(0xffffffffu, c, d);
        const float* sr = g_S + (size_t)cd*FF;
        s0 += sr[lane];
        s1 += sr[lane + 32];
    }
    g_ns[node*FF + lane]      = s0;
    g_ns[node*FF + lane + 32] = s1;
}

// ---------------- 10. dual iterations + quad cost + demand fold ----------------------
__global__ void k_dual(const int* __restrict__ adj, const int* __restrict__ num_nodes,
                       const float* __restrict__ demands){
    __shared__ float red[256];
    int idx = blockIdx.x*256 + threadIdx.x;
    int b = idx >> 15; int node = idx >> 4;
    int a = adj[idx]; int nn = num_nodes[b];
    float mask = (a==nn) ? 1.f : 0.f;
    float valid = 1.f - mask;
    float dv  = g_dualvars[node];
    float dtr = g_dualvars[(b<<11) + a] * valid;
    float dd  = dtr - mask*dv;
    float f = 0.f, ac = 0.f;
    #pragma unroll
    for (int i=0;i<10;i++){
        float g = 2.f*f + dd;
        ac = 0.9f*ac + 0.01f*g;
        f = fmaxf(f - ac, 0.f) * valid;
    }
    float c = f*f + dd*f;
    if ((idx & 15) == 0) c -= dv * demands[node];     // fold dual_demand (once per node)
    red[threadIdx.x] = c; __syncthreads();
    for (int s=128; s>0; s>>=1){ if (threadIdx.x < s) red[threadIdx.x] += red[threadIdx.x+s]; __syncthreads(); }
    if (threadIdx.x == 0) g_dq[blockIdx.x] = red[0];
}

// ---------------- 11. finalize: out[b] = fc - sum(dq partials) ------------------------
__global__ void k_finalize(float* __restrict__ out){
    int w = threadIdx.x >> 5, lane = threadIdx.x & 31;
    if (w < BB){
        float dq = 0.f;
        #pragma unroll
        for (int i=0;i<4;i++) dq += g_dq[w*128 + lane + 32*i];
        #pragma unroll
        for (int o=16;o;o>>=1) dq += __shfl_xor_sync(0xffffffffu, dq, o);
        if (lane == 0) out[w] = g_fc[w] - dq;
    }
}

// ---------------- launcher -------------------------------------------------------------
extern "C" void kernel_launch(void* const* d_in, const int* in_sizes, int n_in,
                              void* d_out, int out_size){
    const float* node_features = (const float*)d_in[0];
    const float* demands       = (const float*)d_in[1];
    const float* emb           = (const float*)d_in[2];
    const float* enc_W         = (const float*)d_in[3];
    const float* enc_b         = (const float*)d_in[4];
    const float* gat_W         = (const float*)d_in[5];
    const float* gat_b         = (const float*)d_in[6];
    const float* gat_a         = (const float*)d_in[7];
    const float* gru_Wx        = (const float*)d_in[8];
    const float* gru_Wh        = (const float*)d_in[9];
    const float* gru_b         = (const float*)d_in[10];
    const float* dec_W1        = (const float*)d_in[11];
    const float* dec_b1        = (const float*)d_in[12];
    const float* dec_W2        = (const float*)d_in[13];
    const float* dec_b2        = (const float*)d_in[14];
    const float* dual_W1       = (const float*)d_in[15];
    const float* dual_b1       = (const float*)d_in[16];
    const float* dual_W2       = (const float*)d_in[17];
    const float* dual_b2       = (const float*)d_in[18];
    const int*   adj           = (const int*)d_in[19];
    const int*   inv_adj       = (const int*)d_in[20];
    const int*   in_idx        = (const int*)d_in[21];
    const int*   rev_idx       = (const int*)d_in[22];
    const int*   num_nodes     = (const int*)d_in[23];
    float* out = (float*)d_out;

    // Lazily created once (first call is the non-captured correctness run); no
    // device memory is allocated by streams/events.
    static cudaStream_t s2 = 0;
    static cudaEvent_t evFork = 0, evJoin = 0;
    if (!s2){
        cudaStreamCreateWithFlags(&s2, cudaStreamNonBlocking);
        cudaEventCreateWithFlags(&evFork, cudaEventDisableTiming);
        cudaEventCreateWithFlags(&evJoin, cudaEventDisableTiming);
    }

    cudaFuncSetAttribute(k_gru,  cudaFuncAttributeMaxDynamicSharedMemorySize, GRU_SMEM);
    cudaFuncSetAttribute(k_gat,  cudaFuncAttributeMaxDynamicSharedMemorySize, GAT_SMEM);
    cudaFuncSetAttribute(k_flow, cudaFuncAttributeMaxDynamicSharedMemorySize, FLOW_SMEM);

    k_enc<<<BV/4 + 16, 256>>>(node_features, emb, enc_W, enc_b);

    for (int l=0; l<2; l++){
        k_gat    <<<NBLK, 512, GAT_SMEM>>>(gat_W, gat_b, gat_a);
        k_attnagg<<<BV/8, 256>>>(adj, num_nodes);
        k_gru    <<<NBLK, 512, GRU_SMEM>>>(gru_Wx, gru_Wh, gru_b);
    }

    // fork: dual branch runs concurrently with the flow branch
    cudaEventRecord(evFork, 0);
    cudaStreamWaitEvent(s2, evFork, 0);

    // dual branch (side stream)
    k_nodestates<<<BV/8, 256, 0, s2>>>(adj, num_nodes);
    k_mlp<<<BV/128, 128, 0, s2>>>(1, dual_W1, dual_b1, dual_W2, dual_b2);
    k_dual<<<BVD/256, 256, 0, s2>>>(adj, num_nodes, demands);
    cudaEventRecord(evJoin, s2);

    // flow branch (main stream)
    k_mlp<<<(NC+127)/128, 128>>>(0, dec_W1, dec_b1, dec_W2, dec_b2);
    k_inattn <<<BV/8, 256>>>(in_idx, inv_adj, adj, num_nodes);
    k_revnorm<<<BV/8, 256>>>(rev_idx, adj, num_nodes);
    k_flow<<<BB, 1024, FLOW_SMEM>>>(demands, inv_adj, in_idx, num_nodes);

    // join, then finalize
    cudaStreamWaitEvent(0, evJoin, 0);
    k_finalize<<<1, 256>>>(out);
}

// round 16
// speedup vs baseline: 1.1931x; 1.0811x over previous
#include <cuda_runtime.h>
#include <math.h>

#define BB 8
#define VV 2048
#define DD 16
#define FF 64
#define EMBD 32
#define HID 32
#define FEAT 16
#define BV (BB*VV)            // 16384
#define BVD (BV*DD)           // 262144
#define VD (VV*DD)            // 32768
#define NC (BV+1)             // 16385 classes (+1 global masked class)
#define NCPAD (65*256)        // 16640
#define NBLK ((NC+127)/128)   // 129 live blocks for gat/gru
#define BIGC 1e9f

typedef unsigned long long ull;

// ---------------- packed f32x2 helpers ----------------------------------------
__device__ __forceinline__ ull pack2(float lo, float hi){
    ull r;
    asm("mov.b64 %0, {%1, %2};" : "=l"(r) : "f"(lo), "f"(hi));
    return r;
}
__device__ __forceinline__ void unpack2(ull v, float& lo, float& hi){
    asm("mov.b64 {%0, %1}, %2;" : "=f"(lo), "=f"(hi) : "l"(v));
}
__device__ __forceinline__ void fma2(ull& d, ull a, ull b){
    asm("fma.rn.f32x2 %0, %1, %2, %0;" : "+l"(d) : "l"(a), "l"(b));
}

// ---------------- scratch (device globals) -----------------------------------
__device__ float g_enc[BV*FF];
__device__ float g_S[NCPAD*FF];      // per-class state
__device__ float g_H[NCPAD*FF];      // per-class tanh(state@W+b)
__device__ float g_sc[NCPAD];        // per-class gat score
__device__ float g_agg[BV*FF];       // per-node agg
__device__ float g_nwc[NCPAD];       // per-class decoder output
__device__ float g_attnin[BVD];
__device__ float g_norm[BVD];
__device__ float g_ns[BV*FF];
__device__ float g_dualvars[BV];
__device__ float g_fc[BB];
__device__ float g_dq[BVD/256];

// ---------------- 1. fused emb-normalize + encoder + S init -------------------
__global__ void k_enc(const float* __restrict__ nf, const float* __restrict__ emb,
                      const float* __restrict__ W, const float* __restrict__ bvec){
    if (blockIdx.x >= BV/4){
        int i = (blockIdx.x - BV/4)*256 + threadIdx.x;     // float4 units, 4096 total
        ((float4*)(g_S + (size_t)BV*FF))[i] = make_float4(0.f,0.f,0.f,0.f);
        return;
    }
    __shared__ float sEmb[4*EMBD];
    int t = threadIdx.x;
    int w = t >> 5, lane = t & 31;
    if (w < 4){
        int v = (blockIdx.x*4 + w) & (VV-1);
        float x = emb[v*EMBD + lane];
        float s = x*x;
        #pragma unroll
        for (int o=16;o;o>>=1) s += __shfl_xor_sync(0xffffffffu, s, o);
        float nrm = sqrtf(s);
        float scale = fminf(1.0f, 1.0f / fmaxf(nrm, 1e-12f));
        sEmb[w*EMBD + lane] = x*scale;
    }
    __syncthreads();
    int nl = t >> 6, f = t & 63;
    int node = blockIdx.x*4 + nl;
    float acc = bvec[f];
    const float* ev = sEmb + nl*EMBD;
    const float* nr = nf + node*FEAT;
    #pragma unroll
    for (int k=0;k<EMBD;k++) acc += ev[k]*W[k*FF+f];
    #pragma unroll
    for (int k=0;k<FEAT;k++) acc += nr[k]*W[(EMBD+k)*FF+f];
    g_enc[node*FF+f] = acc;
    g_S[(size_t)node*FF+f] = acc;
}

// ---------------- 2. per-class GAT: H = tanh(S@W+b), sc = H.a ------------------
// 128 rows/block, 512 threads: 4 threads per row, each 2 f-chunks of 8.
#define GAT_SMEM ((64*64 + 128*64) * (int)sizeof(float))
__global__ void __launch_bounds__(512) k_gat(const float* __restrict__ W,
                                             const float* __restrict__ bvec,
                                             const float* __restrict__ gat_a){
    extern __shared__ float sh[];
    float* Ws   = sh;                 // 64*64
    float* tile = sh + 64*64;         // 128*64 swizzled
    __shared__ float scpart[512];
    int t = threadIdx.x;
    size_t base = (size_t)blockIdx.x * 128;
    for (int i=t;i<64*64;i+=512) Ws[i] = W[i];
    for (int i=t;i<128*64;i+=512){
        int row = i>>6, k = i&63;
        tile[(row<<6) | (k ^ (row&31))] = g_S[base*FF + i];
    }
    __syncthreads();
    int row = t & 127, quarter = t >> 7;
    const float* srow = tile + (row<<6);
    int c = row & 31;
    size_t orow = (base + row) * FF;
    bool live = (base + row) < NC;
    float sc = 0.f;
    #pragma unroll
    for (int fo=0; fo<2; fo++){
        int f = (quarter*2 + fo)*8;
        ull acc[4];
        {
            float b8[8];
            *(float4*)&b8[0] = __ldg((const float4*)(bvec+f));
            *(float4*)&b8[4] = __ldg((const float4*)(bvec+f+4));
            #pragma unroll
            for (int j=0;j<4;j++) acc[j] = pack2(b8[2*j], b8[2*j+1]);
        }
        #pragma unroll 4
        for (int k=0;k<64;k++){
            float skf = srow[k ^ c];
            ull sk2 = pack2(skf, skf);
            const ulonglong2* wp = (const ulonglong2*)(Ws + k*64 + f);
            ulonglong2 w01 = wp[0], w23 = wp[1];
            fma2(acc[0], w01.x, sk2);
            fma2(acc[1], w01.y, sk2);
            fma2(acc[2], w23.x, sk2);
            fma2(acc[3], w23.y, sk2);
        }
        float av[8], hv[8];
        *(float4*)&av[0] = __ldg((const float4*)(gat_a+f));
        *(float4*)&av[4] = __ldg((const float4*)(gat_a+f+4));
        #pragma unroll
        for (int j=0;j<4;j++){
            float a0,a1; unpack2(acc[j], a0, a1);
            hv[2*j]   = tanhf(a0);
            hv[2*j+1] = tanhf(a1);
            sc += hv[2*j]*av[2*j] + hv[2*j+1]*av[2*j+1];
        }
        if (live){
            *(float4*)(g_H + orow + f)     = *(float4*)&hv[0];
            *(float4*)(g_H + orow + f + 4) = *(float4*)&hv[4];
        }
    }
    scpart[t] = sc;
    __syncthreads();
    if (t < 128 && (base + t) < NC)
        g_sc[base + t] = (scpart[t] + scpart[t+128]) + (scpart[t+256] + scpart[t+384]);
}

// ---------------- 3. per-node softmax(D) + agg from class rows ------------------
__global__ void k_attnagg(const int* __restrict__ adj, const int* __restrict__ num_nodes){
    int lane = threadIdx.x & 31;
    int node = blockIdx.x*8 + (threadIdx.x >> 5);
    int b = node >> 11;
    int nn = num_nodes[b];
    int c = 0;
    float sc = -1e30f;
    if (lane < DD){
        int a = adj[node*DD+lane];
        bool m = (a==nn);
        c = m ? BV : ((b<<11)+a);
        sc = g_sc[c] - (m ? BIGC : 0.f);
    }
    float mx = sc;
    #pragma unroll
    for (int o=16;o;o>>=1) mx = fmaxf(mx, __shfl_xor_sync(0xffffffffu, mx, o));
    float e = (lane < DD) ? __expf(sc - mx) : 0.f;
    float sm = e;
    #pragma unroll
    for (int o=16;o;o>>=1) sm += __shfl_xor_sync(0xffffffffu, sm, o);
    float attn = e / sm;
    float a0=0.f, a1=0.f;
    #pragma unroll
    for (int d=0;d<DD;d++){
        float ad = __shfl_sync(0xffffffffu, attn, d);
        int  cd = __shfl_sync(0xffffffffu, c, d);
        const float* hr = g_H + (size_t)cd*FF;
        a0 += ad * hr[lane];
        a1 += ad * hr[lane + 32];
    }
    g_agg[node*FF + lane]      = a0;
    g_agg[node*FF + lane + 32] = a1;
}

// ---------------- 4. per-class GRU: S = GRU(agg+enc, S) -------------------------
// 128 rows/block, 512 threads. Thread = 2 rows (rp, rp+64) x 4 cols x 2 fo.
// Weight loads amortized over 2 rows: per k, 6 LDS.128 + 4 LDS.32 serve 24 fma2
// (vs 14 LDS before) -> LDS wavefronts -29%. z/r gates accumulate x+h fused;
// candidate gate keeps X2/H2 split (nonlinear r*hh).
#define GRU_SMEM ((2*64*192 + 2*128*64) * (int)sizeof(float))
__global__ void __launch_bounds__(512, 1) k_gru(const float* __restrict__ Wx,
                                                const float* __restrict__ Wh,
                                                const float* __restrict__ bvec){
    extern __shared__ float sh[];
    float* Wxs = sh;                   // 64*192
    float* Whs = sh + 64*192;
    float* ms  = sh + 2*64*192;        // 128*64 swizzled
    float* ss  = ms + 128*64;
    int t = threadIdx.x;
    size_t base = (size_t)blockIdx.x * 128;
    {
        const float4* wx4 = (const float4*)Wx;
        const float4* wh4 = (const float4*)Wh;
        float4* wxs4 = (float4*)Wxs;
        float4* whs4 = (float4*)Whs;
        for (int i=t;i<64*192/4;i+=512){ wxs4[i]=wx4[i]; whs4[i]=wh4[i]; }
    }
    for (int i=t;i<128*64;i+=512){
        int row = i>>6, k = i&63;
        size_t gr = base + row;
        int sw = (row<<6) | (k ^ (row&31));
        float mv = 0.f;
        if (gr < BV) mv = g_agg[gr*FF+k] + g_enc[gr*FF+k];
        ms[sw] = mv;
        ss[sw] = g_S[gr*FF + k];
    }
    __syncthreads();
    int rp = t & 63, cg = t >> 6;          // 64 row-pairs x 8 col-groups
    int r0 = rp, r1 = rp + 64;
    int c = rp & 31;                        // (rp+64)&31 == rp&31
    const float* m0 = ms + (r0<<6);
    const float* s0 = ss + (r0<<6);
    const float* m1 = ms + (r1<<6);
    const float* s1 = ss + (r1<<6);
    bool live0 = (base + r0) < NC;
    bool live1 = (base + r1) < NC;
    #pragma unroll
    for (int fo=0; fo<2; fo++){
        int f = cg*8 + fo*4;
        // A[row][grp*2+pair]: grp 0 = z (x+h fused), 1 = r (fused), 2 = X2, 3 = H2
        ull A[2][8];
        #pragma unroll
        for (int r=0;r<2;r++)
            #pragma unroll
            for (int j=0;j<8;j++) A[r][j] = 0ull;
        #pragma unroll 2
        for (int k=0;k<64;k++){
            float mk0f = m0[k ^ c], sk0f = s0[k ^ c];
            float mk1f = m1[k ^ c], sk1f = s1[k ^ c];
            ull mk0 = pack2(mk0f, mk0f), sk0 = pack2(sk0f, sk0f);
            ull mk1 = pack2(mk1f, mk1f), sk1 = pack2(sk1f, sk1f);
            const float* wxp = Wxs + k*192 + f;
            const float* whp = Whs + k*192 + f;
            ulonglong2 x0 = *(const ulonglong2*)(wxp);
            ulonglong2 x1 = *(const ulonglong2*)(wxp+64);
            ulonglong2 x2 = *(const ulonglong2*)(wxp+128);
            ulonglong2 h0 = *(const ulonglong2*)(whp);
            ulonglong2 h1 = *(const ulonglong2*)(whp+64);
            ulonglong2 h2 = *(const ulonglong2*)(whp+128);
            // row 0
            fma2(A[0][0], x0.x, mk0); fma2(A[0][1], x0.y, mk0);
            fma2(A[0][0], h0.x, sk0); fma2(A[0][1], h0.y, sk0);
            fma2(A[0][2], x1.x, mk0); fma2(A[0][3], x1.y, mk0);
            fma2(A[0][2], h1.x, sk0); fma2(A[0][3], h1.y, sk0);
            fma2(A[0][4], x2.x, mk0); fma2(A[0][5], x2.y, mk0);
            fma2(A[0][6], h2.x, sk0); fma2(A[0][7], h2.y, sk0);
            // row 1
            fma2(A[1][0], x0.x, mk1); fma2(A[1][1], x0.y, mk1);
            fma2(A[1][0], h0.x, sk1); fma2(A[1][1], h0.y, sk1);
            fma2(A[1][2], x1.x, mk1); fma2(A[1][3], x1.y, mk1);
            fma2(A[1][2], h1.x, sk1); fma2(A[1][3], h1.y, sk1);
            fma2(A[1][4], x2.x, mk1); fma2(A[1][5], x2.y, mk1);
            fma2(A[1][6], h2.x, sk1); fma2(A[1][7], h2.y, sk1);
        }
        float bz[4], br4[4], bh[4];
        *(float4*)&bz[0]  = __ldg((const float4*)(bvec+f));
        *(float4*)&br4[0] = __ldg((const float4*)(bvec+64+f));
        *(float4*)&bh[0]  = __ldg((const float4*)(bvec+128+f));
        #pragma unroll
        for (int r=0;r<2;r++){
            bool live = r ? live1 : live0;
            if (!live) continue;
            const float* sr = r ? s1 : s0;
            size_t orow = (base + (r ? r1 : r0)) * FF;
            float o[4];
            #pragma unroll
            for (int j=0;j<2;j++){
                float zsa, zsb, rsa, rsb, x2a, x2b, h2a, h2b;
                unpack2(A[r][j],   zsa, zsb);
                unpack2(A[r][2+j], rsa, rsb);
                unpack2(A[r][4+j], x2a, x2b);
                unpack2(A[r][6+j], h2a, h2b);
                float solda = sr[(f+2*j)   ^ c];
                float soldb = sr[(f+2*j+1) ^ c];
                {
                    float z    = 1.f/(1.f + __expf(-(zsa + bz[2*j])));
                    float rr   = 1.f/(1.f + __expf(-(rsa + br4[2*j])));
                    float cand = tanhf(x2a + bh[2*j] + rr*h2a);
                    o[2*j] = z*solda + (1.f - z)*cand;
                }
                {
                    float z    = 1.f/(1.f + __expf(-(zsb + bz[2*j+1])));
                    float rr   = 1.f/(1.f + __expf(-(rsb + br4[2*j+1])));
                    float cand = tanhf(x2b + bh[2*j+1] + rr*h2b);
                    o[2*j+1] = z*soldb + (1.f - z)*cand;
                }
            }
            *(float4*)(g_S + orow + f) = *(float4*)&o[0];
        }
    }
}

// ---------------- 5. 64->32->1 MLP head -------------------------------------------
__global__ void k_mlp(int mode, const float* __restrict__ W1, const float* __restrict__ b1,
                      const float* __restrict__ W2, const float* __restrict__ b2){
    __shared__ float S[128*65];
    __shared__ float W1s[64*32];
    __shared__ float b1s[32], W2s[32];
    const float* in = mode ? g_ns : g_S;
    float* out      = mode ? g_dualvars : g_nwc;
    int nrows       = mode ? BV : NC;
    int t = threadIdx.x;
    int base = blockIdx.x*128;
    for (int i=t;i<2048;i+=128) W1s[i] = W1[i];
    if (t < 32){ b1s[t] = b1[t]; W2s[t] = W2[t]; }
    for (int c=0;c<64;c++){
        int lin = c*128 + t;
        int r = lin >> 6, k = lin & 63;
        S[r*65 + k] = in[(size_t)base*FF + lin];
    }
    __syncthreads();
    if (base + t >= nrows) return;
    float acc[32];
    #pragma unroll
    for (int h=0;h<32;h++) acc[h] = b1s[h];
    const float* myrow = S + t*65;
    for (int k=0;k<64;k++){
        float s = myrow[k];
        #pragma unroll
        for (int h=0;h<32;h++) acc[h] += s*W1s[k*32+h];
    }
    float o = b2[0];
    #pragma unroll
    for (int h=0;h<32;h++) o += tanhf(acc[h])*W2s[h];
    out[base + t] = o;
}

// ---------------- 6. incoming-gather softmax (expand fused) -----------------------
__global__ void k_inattn(const int* __restrict__ in_idx, const int* __restrict__ inv_adj,
                         const int* __restrict__ adj, const int* __restrict__ num_nodes){
    int lane = threadIdx.x & 31;
    int node = blockIdx.x*8 + (threadIdx.x >> 5);
    int b = node >> 11;
    int nn = num_nodes[b];
    float sc = -1e30f;
    if (lane < DD){
        int idx = in_idx[node*DD + lane];
        int a2 = adj[b*VD + idx];
        float inc = g_nwc[(a2==nn) ? BV : ((b<<11)+a2)];
        int ia = inv_adj[node*DD + lane];
        sc = inc - ((ia == nn) ? BIGC : 0.f);
    }
    float mx = sc;
    #pragma unroll
    for (int o=16;o;o>>=1) mx = fmaxf(mx, __shfl_xor_sync(0xffffffffu, mx, o));
    float e = (lane < DD) ? __expf(sc - mx) : 0.f;
    float sm = e;
    #pragma unroll
    for (int o=16;o;o>>=1) sm += __shfl_xor_sync(0xffffffffu, sm, o);
    if (lane < DD) g_attnin[node*DD + lane] = e / sm;
}

// ---------------- 7. rev-gather + masked softmax -> normalized ---------------------
__global__ void k_revnorm(const int* __restrict__ rev_idx, const int* __restrict__ adj,
                          const int* __restrict__ num_nodes){
    int lane = threadIdx.x & 31;
    int node = blockIdx.x*8 + (threadIdx.x >> 5);
    int b = node >> 11;
    float sc = -1e30f;
    if (lane < DD){
        int ridx = rev_idx[node*DD + lane];
        float val = g_attnin[b*VD + ridx];
        int a = adj[node*DD + lane];
        sc = val - ((a == num_nodes[b]) ? BIGC : 0.f);
    }
    float mx = sc;
    #pragma unroll
    for (int o=16;o;o>>=1) mx = fmaxf(mx, __shfl_xor_sync(0xffffffffu, mx, o));
    float e = (lane < DD) ? __expf(sc - mx) : 0.f;
    float sm = e;
    #pragma unroll
    for (int o=16;o;o>>=1) sm += __shfl_xor_sync(0xffffffffu, sm, o);
    if (lane < DD) g_norm[node*DD + lane] = e / sm;
}

// ---------------- 8. flow fixed-point, 1 block/batch ---------------------------------
#define FLOW_SMEM ((3*VV + 1024) * (int)sizeof(float))
__global__ void __launch_bounds__(1024) k_flow(const float* __restrict__ demands,
                                               const int* __restrict__ inv_adj,
                                               const int* __restrict__ in_idx,
                                               const int* __restrict__ num_nodes){
    extern __shared__ float sh[];
    float* ts0 = sh;              // VV
    float* ts1 = ts0 + VV;        // VV
    float* sup = ts1 + VV;        // VV
    float* red = sup + VV;        // 1024
    int b = blockIdx.x, t = threadIdx.x;
    int nn = num_nodes[b];
    unsigned int sp[2][8];        // packed source node indices (16-bit)
    float wreg[2][DD];            // per-edge weights, register-resident
    float nsq[2], supr[2];
    #pragma unroll
    for (int n=0;n<2;n++){
        int v = t + n*1024;
        size_t ebase = ((size_t)b*VV + v)*DD;
        int ia[DD], m[DD];
        #pragma unroll
        for (int d=0;d<DD;d+=4){
            *(int4*)&ia[d] = __ldg((const int4*)(inv_adj + ebase + d));
            *(int4*)&m[d]  = __ldg((const int4*)(in_idx  + ebase + d));
        }
        float nrm[DD];
        #pragma unroll
        for (int d=0;d<DD;d+=4)
            *(float4*)&nrm[d] = __ldg((const float4*)(g_norm + (size_t)b*VD + v*DD + d));
        float q = 0.f;
        #pragma unroll
        for (int d=0;d<DD;d++) q += nrm[d]*nrm[d];
        nsq[n] = q;
        #pragma unroll
        for (int d=0;d<DD;d++){
            wreg[n][d] = (ia[d]==nn) ? 0.f : g_norm[(size_t)b*VD + m[d]];
            int sv = m[d] >> 4;
            if ((d&1)==0) sp[n][d>>1] = (unsigned int)sv;
            else          sp[n][d>>1] |= ((unsigned int)sv) << 16;
        }
        float s = fmaxf(-demands[b*VV + v], 0.f);
        sup[v] = s;
        supr[n] = s;
        ts0[v] = s;
    }
    __syncthreads();
    float* tsA = ts0;
    float* tsB = ts1;
    for (int it=0; it<10; it++){
        float acc[2] = {0.f, 0.f};
        #pragma unroll
        for (int n=0;n<2;n++){
            #pragma unroll
            for (int d=0;d<DD;d++){
                unsigned int pk = sp[n][d>>1];
                int sv = (d&1) ? (pk>>16) : (pk & 0xffff);
                acc[n] += wreg[n][d] * tsA[sv];
            }
        }
        tsB[t]        = supr[0] + acc[0];
        tsB[t + 1024] = supr[1] + acc[1];
        __syncthreads();
        float* tmp = tsA; tsA = tsB; tsB = tmp;
    }
    float c = nsq[0]*tsA[t]*tsA[t] + nsq[1]*tsA[t+1024]*tsA[t+1024];
    red[t] = c; __syncthreads();
    for (int s=512; s>0; s>>=1){ if (t < s) red[t] += red[t+s]; __syncthreads(); }
    if (t == 0) g_fc[b] = red[0];
}

// ---------------- 9. node_states = sum over d of class rows -------------------------
__global__ void k_nodestates(const int* __restrict__ adj, const int* __restrict__ num_nodes){
    int lane = threadIdx.x & 31;
    int node = blockIdx.x*8 + (threadIdx.x >> 5);
    int b = node >> 11;
    int nn = num_nodes[b];
    int c = 0;
    if (lane < DD){
        int a = adj[node*DD+lane];
        c = (a==nn) ? BV : ((b<<11)+a);
    }
    float s0=0.f, s1=0.f;
    #pragma unroll
    for (int d=0;d<DD;d++){
        int cd = __shfl_sync(0xffffffffu, c, d);
        const float* sr = g_S + (size_t)cd*FF;
        s0 += sr[lane];
        s1 += sr[lane + 32];
    }
    g_ns[node*FF + lane]      = s0;
    g_ns[node*FF + lane + 32] = s1;
}

// ---------------- 10. dual iterations + quad cost + demand fold ----------------------
__global__ void k_dual(const int* __restrict__ adj, const int* __restrict__ num_nodes,
                       const float* __restrict__ demands){
    __shared__ float red[256];
    int idx = blockIdx.x*256 + threadIdx.x;
    int b = idx >> 15; int node = idx >> 4;
    int a = adj[idx]; int nn = num_nodes[b];
    float mask = (a==nn) ? 1.f : 0.f;
    float valid = 1.f - mask;
    float dv  = g_dualvars[node];
    float dtr = g_dualvars[(b<<11) + a] * valid;
    float dd  = dtr - mask*dv;
    float f = 0.f, ac = 0.f;
    #pragma unroll
    for (int i=0;i<10;i++){
        float g = 2.f*f + dd;
        ac = 0.9f*ac + 0.01f*g;
        f = fmaxf(f - ac, 0.f) * valid;
    }
    float c = f*f + dd*f;
    if ((idx & 15) == 0) c -= dv * demands[node];     // fold dual_demand (once per node)
    red[threadIdx.x] = c; __syncthreads();
    for (int s=128; s>0; s>>=1){ if (threadIdx.x < s) red[threadIdx.x] += red[threadIdx.x+s]; __syncthreads(); }
    if (threadIdx.x == 0) g_dq[blockIdx.x] = red[0];
}

// ---------------- 11. finalize: out[b] = fc - sum(dq partials) ------------------------
__global__ void k_finalize(float* __restrict__ out){
    int w = threadIdx.x >> 5, lane = threadIdx.x & 31;
    if (w < BB){
        float dq = 0.f;
        #pragma unroll
        for (int i=0;i<4;i++) dq += g_dq[w*128 + lane + 32*i];
        #pragma unroll
        for (int o=16;o;o>>=1) dq += __shfl_xor_sync(0xffffffffu, dq, o);
        if (lane == 0) out[w] = g_fc[w] - dq;
    }
}

// ---------------- launcher -------------------------------------------------------------
extern "C" void kernel_launch(void* const* d_in, const int* in_sizes, int n_in,
                              void* d_out, int out_size){
    const float* node_features = (const float*)d_in[0];
    const float* demands       = (const float*)d_in[1];
    const float* emb           = (const float*)d_in[2];
    const float* enc_W         = (const float*)d_in[3];
    const float* enc_b         = (const float*)d_in[4];
    const float* gat_W         = (const float*)d_in[5];
    const float* gat_b         = (const float*)d_in[6];
    const float* gat_a         = (const float*)d_in[7];
    const float* gru_Wx        = (const float*)d_in[8];
    const float* gru_Wh        = (const float*)d_in[9];
    const float* gru_b         = (const float*)d_in[10];
    const float* dec_W1        = (const float*)d_in[11];
    const float* dec_b1        = (const float*)d_in[12];
    const float* dec_W2        = (const float*)d_in[13];
    const float* dec_b2        = (const float*)d_in[14];
    const float* dual_W1       = (const float*)d_in[15];
    const float* dual_b1       = (const float*)d_in[16];
    const float* dual_W2       = (const float*)d_in[17];
    const float* dual_b2       = (const float*)d_in[18];
    const int*   adj           = (const int*)d_in[19];
    const int*   inv_adj       = (const int*)d_in[20];
    const int*   in_idx        = (const int*)d_in[21];
    const int*   rev_idx       = (const int*)d_in[22];
    const int*   num_nodes     = (const int*)d_in[23];
    float* out = (float*)d_out;

    // Lazily created once (first call is the non-captured correctness run); no
    // device memory is allocated by streams/events.
    static cudaStream_t s2 = 0;
    static cudaEvent_t evFork = 0, evJoin = 0;
    if (!s2){
        cudaStreamCreateWithFlags(&s2, cudaStreamNonBlocking);
        cudaEventCreateWithFlags(&evFork, cudaEventDisableTiming);
        cudaEventCreateWithFlags(&evJoin, cudaEventDisableTiming);
    }

    cudaFuncSetAttribute(k_gru,  cudaFuncAttributeMaxDynamicSharedMemorySize, GRU_SMEM);
    cudaFuncSetAttribute(k_gat,  cudaFuncAttributeMaxDynamicSharedMemorySize, GAT_SMEM);
    cudaFuncSetAttribute(k_flow, cudaFuncAttributeMaxDynamicSharedMemorySize, FLOW_SMEM);

    k_enc<<<BV/4 + 16, 256>>>(node_features, emb, enc_W, enc_b);

    for (int l=0; l<2; l++){
        k_gat    <<<NBLK, 512, GAT_SMEM>>>(gat_W, gat_b, gat_a);
        k_attnagg<<<BV/8, 256>>>(adj, num_nodes);
        k_gru    <<<NBLK, 512, GRU_SMEM>>>(gru_Wx, gru_Wh, gru_b);
    }

    // fork: dual branch runs concurrently with the flow branch
    cudaEventRecord(evFork, 0);
    cudaStreamWaitEvent(s2, evFork, 0);

    // dual branch (side stream)
    k_nodestates<<<BV/8, 256, 0, s2>>>(adj, num_nodes);
    k_mlp<<<BV/128, 128, 0, s2>>>(1, dual_W1, dual_b1, dual_W2, dual_b2);
    k_dual<<<BVD/256, 256, 0, s2>>>(adj, num_nodes, demands);
    cudaEventRecord(evJoin, s2);

    // flow branch (main stream)
    k_mlp<<<(NC+127)/128, 128>>>(0, dec_W1, dec_b1, dec_W2, dec_b2);
    k_inattn <<<BV/8, 256>>>(in_idx, inv_adj, adj, num_nodes);
    k_revnorm<<<BV/8, 256>>>(rev_idx, adj, num_nodes);
    k_flow<<<BB, 1024, FLOW_SMEM>>>(demands, inv_adj, in_idx, num_nodes);

    // join, then finalize
    cudaStreamWaitEvent(0, evJoin, 0);
    k_finalize<<<1, 256>>>(out);
}

// round 17
// speedup vs baseline: 1.2021x; 1.0075x over previous
#include <cuda_runtime.h>
#include <math.h>

#define BB 8
#define VV 2048
#define DD 16
#define FF 64
#define EMBD 32
#define HID 32
#define FEAT 16
#define BV (BB*VV)            // 16384
#define BVD (BV*DD)           // 262144
#define VD (VV*DD)            // 32768
#define NC (BV+1)             // 16385 classes (+1 global masked class)
#define NCPAD (65*256)        // 16640
#define NBLK ((NC+127)/128)   // 129 live blocks for gat/gru
#define BIGC 1e9f

typedef unsigned long long ull;

// ---------------- packed f32x2 helpers ----------------------------------------
__device__ __forceinline__ ull pack2(float lo, float hi){
    ull r;
    asm("mov.b64 %0, {%1, %2};" : "=l"(r) : "f"(lo), "f"(hi));
    return r;
}
__device__ __forceinline__ void unpack2(ull v, float& lo, float& hi){
    asm("mov.b64 {%0, %1}, %2;" : "=f"(lo), "=f"(hi) : "l"(v));
}
__device__ __forceinline__ void fma2(ull& d, ull a, ull b){
    asm("fma.rn.f32x2 %0, %1, %2, %0;" : "+l"(d) : "l"(a), "l"(b));
}

// ---------------- scratch (device globals) -----------------------------------
__device__ float g_enc[BV*FF];
__device__ float g_S[NCPAD*FF];      // per-class state
__device__ float g_H[NCPAD*FF];      // per-class tanh(state@W+b)
__device__ float g_sc[NCPAD];        // per-class gat score
__device__ float g_agg[BV*FF];       // per-node agg
__device__ float g_nwc[NCPAD];       // per-class decoder output
__device__ float g_attnin[BVD];
__device__ float g_norm[BVD];
__device__ float g_ns[BV*FF];
__device__ float g_dualvars[BV];
__device__ float g_fc[BB];
__device__ float g_dq[BVD/256];

// ---------------- 1. fused emb-normalize + encoder + S init -------------------
__global__ void k_enc(const float* __restrict__ nf, const float* __restrict__ emb,
                      const float* __restrict__ W, const float* __restrict__ bvec){
    if (blockIdx.x >= BV/4){
        int i = (blockIdx.x - BV/4)*256 + threadIdx.x;     // float4 units, 4096 total
        ((float4*)(g_S + (size_t)BV*FF))[i] = make_float4(0.f,0.f,0.f,0.f);
        return;
    }
    __shared__ float sEmb[4*EMBD];
    int t = threadIdx.x;
    int w = t >> 5, lane = t & 31;
    if (w < 4){
        int v = (blockIdx.x*4 + w) & (VV-1);
        float x = emb[v*EMBD + lane];
        float s = x*x;
        #pragma unroll
        for (int o=16;o;o>>=1) s += __shfl_xor_sync(0xffffffffu, s, o);
        float nrm = sqrtf(s);
        float scale = fminf(1.0f, 1.0f / fmaxf(nrm, 1e-12f));
        sEmb[w*EMBD + lane] = x*scale;
    }
    __syncthreads();
    int nl = t >> 6, f = t & 63;
    int node = blockIdx.x*4 + nl;
    float acc = bvec[f];
    const float* ev = sEmb + nl*EMBD;
    const float* nr = nf + node*FEAT;
    #pragma unroll
    for (int k=0;k<EMBD;k++) acc += ev[k]*W[k*FF+f];
    #pragma unroll
    for (int k=0;k<FEAT;k++) acc += nr[k]*W[(EMBD+k)*FF+f];
    g_enc[node*FF+f] = acc;
    g_S[(size_t)node*FF+f] = acc;
}

// ---------------- 2. per-class GAT: H = tanh(S@W+b), sc = H.a ------------------
// 128 rows/block, 512 threads. Thread = 2 rows (rp, rp+64) x 8 cols.
// Per k: 2 LDS.32 + 2 LDS.128 serve 8 fma2 (weights amortized over 2 rows).
#define GAT_SMEM ((64*64 + 128*64) * (int)sizeof(float))
__global__ void __launch_bounds__(512) k_gat(const float* __restrict__ W,
                                             const float* __restrict__ bvec,
                                             const float* __restrict__ gat_a){
    extern __shared__ float sh[];
    float* Ws   = sh;                 // 64*64
    float* tile = sh + 64*64;         // 128*64 swizzled
    __shared__ float scpart[128*8];
    int t = threadIdx.x;
    size_t base = (size_t)blockIdx.x * 128;
    for (int i=t;i<64*64;i+=512) Ws[i] = W[i];
    for (int i=t;i<128*64;i+=512){
        int row = i>>6, k = i&63;
        tile[(row<<6) | (k ^ (row&31))] = g_S[base*FF + i];
    }
    __syncthreads();
    int rp = t & 63, cg = t >> 6;         // 64 row-pairs x 8 col-groups
    int r0 = rp, r1 = rp + 64;
    int c = rp & 31;
    const float* s0 = tile + (r0<<6);
    const float* s1 = tile + (r1<<6);
    int f = cg*8;
    ull a0[4], a1[4];
    {
        float b8[8];
        *(float4*)&b8[0] = __ldg((const float4*)(bvec+f));
        *(float4*)&b8[4] = __ldg((const float4*)(bvec+f+4));
        #pragma unroll
        for (int j=0;j<4;j++){ a0[j] = pack2(b8[2*j], b8[2*j+1]); a1[j] = a0[j]; }
    }
    #pragma unroll 4
    for (int k=0;k<64;k++){
        float v0 = s0[k ^ c];
        float v1 = s1[k ^ c];
        ull p0 = pack2(v0, v0);
        ull p1 = pack2(v1, v1);
        const ulonglong2* wp = (const ulonglong2*)(Ws + k*64 + f);
        ulonglong2 w01 = wp[0], w23 = wp[1];
        fma2(a0[0], w01.x, p0); fma2(a0[1], w01.y, p0);
        fma2(a0[2], w23.x, p0); fma2(a0[3], w23.y, p0);
        fma2(a1[0], w01.x, p1); fma2(a1[1], w01.y, p1);
        fma2(a1[2], w23.x, p1); fma2(a1[3], w23.y, p1);
    }
    float av[8];
    *(float4*)&av[0] = __ldg((const float4*)(gat_a+f));
    *(float4*)&av[4] = __ldg((const float4*)(gat_a+f+4));
    float hv0[8], hv1[8];
    float sc0 = 0.f, sc1 = 0.f;
    #pragma unroll
    for (int j=0;j<4;j++){
        float xa, xb;
        unpack2(a0[j], xa, xb);
        hv0[2*j] = tanhf(xa); hv0[2*j+1] = tanhf(xb);
        sc0 += hv0[2*j]*av[2*j] + hv0[2*j+1]*av[2*j+1];
        unpack2(a1[j], xa, xb);
        hv1[2*j] = tanhf(xa); hv1[2*j+1] = tanhf(xb);
        sc1 += hv1[2*j]*av[2*j] + hv1[2*j+1]*av[2*j+1];
    }
    bool live0 = (base + r0) < NC;
    bool live1 = (base + r1) < NC;
    if (live0){
        size_t orow = (base + r0) * FF;
        *(float4*)(g_H + orow + f)     = *(float4*)&hv0[0];
        *(float4*)(g_H + orow + f + 4) = *(float4*)&hv0[4];
    }
    if (live1){
        size_t orow = (base + r1) * FF;
        *(float4*)(g_H + orow + f)     = *(float4*)&hv1[0];
        *(float4*)(g_H + orow + f + 4) = *(float4*)&hv1[4];
    }
    scpart[r0*8 + cg] = sc0;
    scpart[r1*8 + cg] = sc1;
    __syncthreads();
    if (t < 128 && (base + t) < NC){
        const float* sp = scpart + t*8;
        float s = ((sp[0] + sp[1]) + (sp[2] + sp[3])) + ((sp[4] + sp[5]) + (sp[6] + sp[7]));
        g_sc[base + t] = s;
    }
}

// ---------------- 3. per-node softmax(D) + agg from class rows ------------------
__global__ void k_attnagg(const int* __restrict__ adj, const int* __restrict__ num_nodes){
    int lane = threadIdx.x & 31;
    int node = blockIdx.x*8 + (threadIdx.x >> 5);
    int b = node >> 11;
    int nn = num_nodes[b];
    int c = 0;
    float sc = -1e30f;
    if (lane < DD){
        int a = adj[node*DD+lane];
        bool m = (a==nn);
        c = m ? BV : ((b<<11)+a);
        sc = g_sc[c] - (m ? BIGC : 0.f);
    }
    float mx = sc;
    #pragma unroll
    for (int o=16;o;o>>=1) mx = fmaxf(mx, __shfl_xor_sync(0xffffffffu, mx, o));
    float e = (lane < DD) ? __expf(sc - mx) : 0.f;
    float sm = e;
    #pragma unroll
    for (int o=16;o;o>>=1) sm += __shfl_xor_sync(0xffffffffu, sm, o);
    float attn = e / sm;
    float a0=0.f, a1=0.f;
    #pragma unroll
    for (int d=0;d<DD;d++){
        float ad = __shfl_sync(0xffffffffu, attn, d);
        int  cd = __shfl_sync(0xffffffffu, c, d);
        const float* hr = g_H + (size_t)cd*FF;
        a0 += ad * hr[lane];
        a1 += ad * hr[lane + 32];
    }
    g_agg[node*FF + lane]      = a0;
    g_agg[node*FF + lane + 32] = a1;
}

// ---------------- 4. per-class GRU: S = GRU(agg+enc, S) -------------------------
// 128 rows/block, 512 threads. Thread = 2 rows (rp, rp+64) x 4 cols x 2 fo.
#define GRU_SMEM ((2*64*192 + 2*128*64) * (int)sizeof(float))
__global__ void __launch_bounds__(512, 1) k_gru(const float* __restrict__ Wx,
                                                const float* __restrict__ Wh,
                                                const float* __restrict__ bvec){
    extern __shared__ float sh[];
    float* Wxs = sh;                   // 64*192
    float* Whs = sh + 64*192;
    float* ms  = sh + 2*64*192;        // 128*64 swizzled
    float* ss  = ms + 128*64;
    int t = threadIdx.x;
    size_t base = (size_t)blockIdx.x * 128;
    {
        const float4* wx4 = (const float4*)Wx;
        const float4* wh4 = (const float4*)Wh;
        float4* wxs4 = (float4*)Wxs;
        float4* whs4 = (float4*)Whs;
        for (int i=t;i<64*192/4;i+=512){ wxs4[i]=wx4[i]; whs4[i]=wh4[i]; }
    }
    for (int i=t;i<128*64;i+=512){
        int row = i>>6, k = i&63;
        size_t gr = base + row;
        int sw = (row<<6) | (k ^ (row&31));
        float mv = 0.f;
        if (gr < BV) mv = g_agg[gr*FF+k] + g_enc[gr*FF+k];
        ms[sw] = mv;
        ss[sw] = g_S[gr*FF + k];
    }
    __syncthreads();
    int rp = t & 63, cg = t >> 6;          // 64 row-pairs x 8 col-groups
    int r0 = rp, r1 = rp + 64;
    int c = rp & 31;                        // (rp+64)&31 == rp&31
    const float* m0 = ms + (r0<<6);
    const float* s0 = ss + (r0<<6);
    const float* m1 = ms + (r1<<6);
    const float* s1 = ss + (r1<<6);
    bool live0 = (base + r0) < NC;
    bool live1 = (base + r1) < NC;
    #pragma unroll
    for (int fo=0; fo<2; fo++){
        int f = cg*8 + fo*4;
        // A[row][grp*2+pair]: grp 0 = z (x+h fused), 1 = r (fused), 2 = X2, 3 = H2
        ull A[2][8];
        #pragma unroll
        for (int r=0;r<2;r++)
            #pragma unroll
            for (int j=0;j<8;j++) A[r][j] = 0ull;
        #pragma unroll 2
        for (int k=0;k<64;k++){
            float mk0f = m0[k ^ c], sk0f = s0[k ^ c];
            float mk1f = m1[k ^ c], sk1f = s1[k ^ c];
            ull mk0 = pack2(mk0f, mk0f), sk0 = pack2(sk0f, sk0f);
            ull mk1 = pack2(mk1f, mk1f), sk1 = pack2(sk1f, sk1f);
            const float* wxp = Wxs + k*192 + f;
            const float* whp = Whs + k*192 + f;
            ulonglong2 x0 = *(const ulonglong2*)(wxp);
            ulonglong2 x1 = *(const ulonglong2*)(wxp+64);
            ulonglong2 x2 = *(const ulonglong2*)(wxp+128);
            ulonglong2 h0 = *(const ulonglong2*)(whp);
            ulonglong2 h1 = *(const ulonglong2*)(whp+64);
            ulonglong2 h2 = *(const ulonglong2*)(whp+128);
            // row 0
            fma2(A[0][0], x0.x, mk0); fma2(A[0][1], x0.y, mk0);
            fma2(A[0][0], h0.x, sk0); fma2(A[0][1], h0.y, sk0);
            fma2(A[0][2], x1.x, mk0); fma2(A[0][3], x1.y, mk0);
            fma2(A[0][2], h1.x, sk0); fma2(A[0][3], h1.y, sk0);
            fma2(A[0][4], x2.x, mk0); fma2(A[0][5], x2.y, mk0);
            fma2(A[0][6], h2.x, sk0); fma2(A[0][7], h2.y, sk0);
            // row 1
            fma2(A[1][0], x0.x, mk1); fma2(A[1][1], x0.y, mk1);
            fma2(A[1][0], h0.x, sk1); fma2(A[1][1], h0.y, sk1);
            fma2(A[1][2], x1.x, mk1); fma2(A[1][3], x1.y, mk1);
            fma2(A[1][2], h1.x, sk1); fma2(A[1][3], h1.y, sk1);
            fma2(A[1][4], x2.x, mk1); fma2(A[1][5], x2.y, mk1);
            fma2(A[1][6], h2.x, sk1); fma2(A[1][7], h2.y, sk1);
        }
        float bz[4], br4[4], bh[4];
        *(float4*)&bz[0]  = __ldg((const float4*)(bvec+f));
        *(float4*)&br4[0] = __ldg((const float4*)(bvec+64+f));
        *(float4*)&bh[0]  = __ldg((const float4*)(bvec+128+f));
        #pragma unroll
        for (int r=0;r<2;r++){
            bool live = r ? live1 : live0;
            if (!live) continue;
            const float* sr = r ? s1 : s0;
            size_t orow = (base + (r ? r1 : r0)) * FF;
            float o[4];
            #pragma unroll
            for (int j=0;j<2;j++){
                float zsa, zsb, rsa, rsb, x2a, x2b, h2a, h2b;
                unpack2(A[r][j],   zsa, zsb);
                unpack2(A[r][2+j], rsa, rsb);
                unpack2(A[r][4+j], x2a, x2b);
                unpack2(A[r][6+j], h2a, h2b);
                float solda = sr[(f+2*j)   ^ c];
                float soldb = sr[(f+2*j+1) ^ c];
                {
                    float z    = 1.f/(1.f + __expf(-(zsa + bz[2*j])));
                    float rr   = 1.f/(1.f + __expf(-(rsa + br4[2*j])));
                    float cand = tanhf(x2a + bh[2*j] + rr*h2a);
                    o[2*j] = z*solda + (1.f - z)*cand;
                }
                {
                    float z    = 1.f/(1.f + __expf(-(zsb + bz[2*j+1])));
                    float rr   = 1.f/(1.f + __expf(-(rsb + br4[2*j+1])));
                    float cand = tanhf(x2b + bh[2*j+1] + rr*h2b);
                    o[2*j+1] = z*soldb + (1.f - z)*cand;
                }
            }
            *(float4*)(g_S + orow + f) = *(float4*)&o[0];
        }
    }
}

// ---------------- 5. 64->32->1 MLP head -------------------------------------------
__global__ void k_mlp(int mode, const float* __restrict__ W1, const float* __restrict__ b1,
                      const float* __restrict__ W2, const float* __restrict__ b2){
    __shared__ float S[128*65];
    __shared__ float W1s[64*32];
    __shared__ float b1s[32], W2s[32];
    const float* in = mode ? g_ns : g_S;
    float* out      = mode ? g_dualvars : g_nwc;
    int nrows       = mode ? BV : NC;
    int t = threadIdx.x;
    int base = blockIdx.x*128;
    for (int i=t;i<2048;i+=128) W1s[i] = W1[i];
    if (t < 32){ b1s[t] = b1[t]; W2s[t] = W2[t]; }
    for (int c=0;c<64;c++){
        int lin = c*128 + t;
        int r = lin >> 6, k = lin & 63;
        S[r*65 + k] = in[(size_t)base*FF + lin];
    }
    __syncthreads();
    if (base + t >= nrows) return;
    float acc[32];
    #pragma unroll
    for (int h=0;h<32;h++) acc[h] = b1s[h];
    const float* myrow = S + t*65;
    for (int k=0;k<64;k++){
        float s = myrow[k];
        #pragma unroll
        for (int h=0;h<32;h++) acc[h] += s*W1s[k*32+h];
    }
    float o = b2[0];
    #pragma unroll
    for (int h=0;h<32;h++) o += tanhf(acc[h])*W2s[h];
    out[base + t] = o;
}

// ---------------- 6. incoming-gather softmax (expand fused) -----------------------
__global__ void k_inattn(const int* __restrict__ in_idx, const int* __restrict__ inv_adj,
                         const int* __restrict__ adj, const int* __restrict__ num_nodes){
    int lane = threadIdx.x & 31;
    int node = blockIdx.x*8 + (threadIdx.x >> 5);
    int b = node >> 11;
    int nn = num_nodes[b];
    float sc = -1e30f;
    if (lane < DD){
        int idx = in_idx[node*DD + lane];
        int a2 = adj[b*VD + idx];
        float inc = g_nwc[(a2==nn) ? BV : ((b<<11)+a2)];
        int ia = inv_adj[node*DD + lane];
        sc = inc - ((ia == nn) ? BIGC : 0.f);
    }
    float mx = sc;
    #pragma unroll
    for (int o=16;o;o>>=1) mx = fmaxf(mx, __shfl_xor_sync(0xffffffffu, mx, o));
    float e = (lane < DD) ? __expf(sc - mx) : 0.f;
    float sm = e;
    #pragma unroll
    for (int o=16;o;o>>=1) sm += __shfl_xor_sync(0xffffffffu, sm, o);
    if (lane < DD) g_attnin[node*DD + lane] = e / sm;
}

// ---------------- 7. rev-gather + masked softmax -> normalized ---------------------
__global__ void k_revnorm(const int* __restrict__ rev_idx, const int* __restrict__ adj,
                          const int* __restrict__ num_nodes){
    int lane = threadIdx.x & 31;
    int node = blockIdx.x*8 + (threadIdx.x >> 5);
    int b = node >> 11;
    float sc = -1e30f;
    if (lane < DD){
        int ridx = rev_idx[node*DD + lane];
        float val = g_attnin[b*VD + ridx];
        int a = adj[node*DD + lane];
        sc = val - ((a == num_nodes[b]) ? BIGC : 0.f);
    }
    float mx = sc;
    #pragma unroll
    for (int o=16;o;o>>=1) mx = fmaxf(mx, __shfl_xor_sync(0xffffffffu, mx, o));
    float e = (lane < DD) ? __expf(sc - mx) : 0.f;
    float sm = e;
    #pragma unroll
    for (int o=16;o;o>>=1) sm += __shfl_xor_sync(0xffffffffu, sm, o);
    if (lane < DD) g_norm[node*DD + lane] = e / sm;
}

// ---------------- 8. flow fixed-point, 1 block/batch ---------------------------------
#define FLOW_SMEM ((3*VV + 1024) * (int)sizeof(float))
__global__ void __launch_bounds__(1024) k_flow(const float* __restrict__ demands,
                                               const int* __restrict__ inv_adj,
                                               const int* __restrict__ in_idx,
                                               const int* __restrict__ num_nodes){
    extern __shared__ float sh[];
    float* ts0 = sh;              // VV
    float* ts1 = ts0 + VV;        // VV
    float* sup = ts1 + VV;        // VV
    float* red = sup + VV;        // 1024
    int b = blockIdx.x, t = threadIdx.x;
    int nn = num_nodes[b];
    unsigned int sp[2][8];        // packed source node indices (16-bit)
    float wreg[2][DD];            // per-edge weights, register-resident
    float nsq[2], supr[2];
    #pragma unroll
    for (int n=0;n<2;n++){
        int v = t + n*1024;
        size_t ebase = ((size_t)b*VV + v)*DD;
        int ia[DD], m[DD];
        #pragma unroll
        for (int d=0;d<DD;d+=4){
            *(int4*)&ia[d] = __ldg((const int4*)(inv_adj + ebase + d));
            *(int4*)&m[d]  = __ldg((const int4*)(in_idx  + ebase + d));
        }
        float nrm[DD];
        #pragma unroll
        for (int d=0;d<DD;d+=4)
            *(float4*)&nrm[d] = __ldg((const float4*)(g_norm + (size_t)b*VD + v*DD + d));
        float q = 0.f;
        #pragma unroll
        for (int d=0;d<DD;d++) q += nrm[d]*nrm[d];
        nsq[n] = q;
        #pragma unroll
        for (int d=0;d<DD;d++){
            wreg[n][d] = (ia[d]==nn) ? 0.f : g_norm[(size_t)b*VD + m[d]];
            int sv = m[d] >> 4;
            if ((d&1)==0) sp[n][d>>1] = (unsigned int)sv;
            else          sp[n][d>>1] |= ((unsigned int)sv) << 16;
        }
        float s = fmaxf(-demands[b*VV + v], 0.f);
        sup[v] = s;
        supr[n] = s;
        ts0[v] = s;
    }
    __syncthreads();
    float* tsA = ts0;
    float* tsB = ts1;
    for (int it=0; it<10; it++){
        float acc[2] = {0.f, 0.f};
        #pragma unroll
        for (int n=0;n<2;n++){
            #pragma unroll
            for (int d=0;d<DD;d++){
                unsigned int pk = sp[n][d>>1];
                int sv = (d&1) ? (pk>>16) : (pk & 0xffff);
                acc[n] += wreg[n][d] * tsA[sv];
            }
        }
        tsB[t]        = supr[0] + acc[0];
        tsB[t + 1024] = supr[1] + acc[1];
        __syncthreads();
        float* tmp = tsA; tsA = tsB; tsB = tmp;
    }
    float c = nsq[0]*tsA[t]*tsA[t] + nsq[1]*tsA[t+1024]*tsA[t+1024];
    red[t] = c; __syncthreads();
    for (int s=512; s>0; s>>=1){ if (t < s) red[t] += red[t+s]; __syncthreads(); }
    if (t == 0) g_fc[b] = red[0];
}

// ---------------- 9. node_states = sum over d of class rows -------------------------
__global__ void k_nodestates(const int* __restrict__ adj, const int* __restrict__ num_nodes){
    int lane = threadIdx.x & 31;
    int node = blockIdx.x*8 + (threadIdx.x >> 5);
    int b = node >> 11;
    int nn = num_nodes[b];
    int c = 0;
    if (lane < DD){
        int a = adj[node*DD+lane];
        c = (a==nn) ? BV : ((b<<11)+a);
    }
    float s0=0.f, s1=0.f;
    #pragma unroll
    for (int d=0;d<DD;d++){
        int cd = __shfl_sync(0xffffffffu, c, d);
        const float* sr = g_S + (size_t)cd*FF;
        s0 += sr[lane];
        s1 += sr[lane + 32];
    }
    g_ns[node*FF + lane]      = s0;
    g_ns[node*FF + lane + 32] = s1;
}

// ---------------- 10. dual iterations + quad cost + demand fold ----------------------
__global__ void k_dual(const int* __restrict__ adj, const int* __restrict__ num_nodes,
                       const float* __restrict__ demands){
    __shared__ float red[256];
    int idx = blockIdx.x*256 + threadIdx.x;
    int b = idx >> 15; int node = idx >> 4;
    int a = adj[idx]; int nn = num_nodes[b];
    float mask = (a==nn) ? 1.f : 0.f;
    float valid = 1.f - mask;
    float dv  = g_dualvars[node];
    float dtr = g_dualvars[(b<<11) + a] * valid;
    float dd  = dtr - mask*dv;
    float f = 0.f, ac = 0.f;
    #pragma unroll
    for (int i=0;i<10;i++){
        float g = 2.f*f + dd;
        ac = 0.9f*ac + 0.01f*g;
        f = fmaxf(f - ac, 0.f) * valid;
    }
    float c = f*f + dd*f;
    if ((idx & 15) == 0) c -= dv * demands[node];     // fold dual_demand (once per node)
    red[threadIdx.x] = c; __syncthreads();
    for (int s=128; s>0; s>>=1){ if (threadIdx.x < s) red[threadIdx.x] += red[threadIdx.x+s]; __syncthreads(); }
    if (threadIdx.x == 0) g_dq[blockIdx.x] = red[0];
}

// ---------------- 11. finalize: out[b] = fc - sum(dq partials) ------------------------
__global__ void k_finalize(float* __restrict__ out){
    int w = threadIdx.x >> 5, lane = threadIdx.x & 31;
    if (w < BB){
        float dq = 0.f;
        #pragma unroll
        for (int i=0;i<4;i++) dq += g_dq[w*128 + lane + 32*i];
        #pragma unroll
        for (int o=16;o;o>>=1) dq += __shfl_xor_sync(0xffffffffu, dq, o);
        if (lane == 0) out[w] = g_fc[w] - dq;
    }
}

// ---------------- launcher -------------------------------------------------------------
extern "C" void kernel_launch(void* const* d_in, const int* in_sizes, int n_in,
                              void* d_out, int out_size){
    const float* node_features = (const float*)d_in[0];
    const float* demands       = (const float*)d_in[1];
    const float* emb           = (const float*)d_in[2];
    const float* enc_W         = (const float*)d_in[3];
    const float* enc_b         = (const float*)d_in[4];
    const float* gat_W         = (const float*)d_in[5];
    const float* gat_b         = (const float*)d_in[6];
    const float* gat_a         = (const float*)d_in[7];
    const float* gru_Wx        = (const float*)d_in[8];
    const float* gru_Wh        = (const float*)d_in[9];
    const float* gru_b         = (const float*)d_in[10];
    const float* dec_W1        = (const float*)d_in[11];
    const float* dec_b1        = (const float*)d_in[12];
    const float* dec_W2        = (const float*)d_in[13];
    const float* dec_b2        = (const float*)d_in[14];
    const float* dual_W1       = (const float*)d_in[15];
    const float* dual_b1       = (const float*)d_in[16];
    const float* dual_W2       = (const float*)d_in[17];
    const float* dual_b2       = (const float*)d_in[18];
    const int*   adj           = (const int*)d_in[19];
    const int*   inv_adj       = (const int*)d_in[20];
    const int*   in_idx        = (const int*)d_in[21];
    const int*   rev_idx       = (const int*)d_in[22];
    const int*   num_nodes     = (const int*)d_in[23];
    float* out = (float*)d_out;

    // Lazily created once (first call is the non-captured correctness run); no
    // device memory is allocated by streams/events.
    static cudaStream_t s2 = 0;
    static cudaEvent_t evFork = 0, evJoin = 0;
    if (!s2){
        cudaStreamCreateWithFlags(&s2, cudaStreamNonBlocking);
        cudaEventCreateWithFlags(&evFork, cudaEventDisableTiming);
        cudaEventCreateWithFlags(&evJoin, cudaEventDisableTiming);
    }

    cudaFuncSetAttribute(k_gru,  cudaFuncAttributeMaxDynamicSharedMemorySize, GRU_SMEM);
    cudaFuncSetAttribute(k_gat,  cudaFuncAttributeMaxDynamicSharedMemorySize, GAT_SMEM);
    cudaFuncSetAttribute(k_flow, cudaFuncAttributeMaxDynamicSharedMemorySize, FLOW_SMEM);

    k_enc<<<BV/4 + 16, 256>>>(node_features, emb, enc_W, enc_b);

    for (int l=0; l<2; l++){
        k_gat    <<<NBLK, 512, GAT_SMEM>>>(gat_W, gat_b, gat_a);
        k_attnagg<<<BV/8, 256>>>(adj, num_nodes);
        k_gru    <<<NBLK, 512, GRU_SMEM>>>(gru_Wx, gru_Wh, gru_b);
    }

    // fork: dual branch runs concurrently with the flow branch
    cudaEventRecord(evFork, 0);
    cudaStreamWaitEvent(s2, evFork, 0);

    // dual branch (side stream)
    k_nodestates<<<BV/8, 256, 0, s2>>>(adj, num_nodes);
    k_mlp<<<BV/128, 128, 0, s2>>>(1, dual_W1, dual_b1, dual_W2, dual_b2);
    k_dual<<<BVD/256, 256, 0, s2>>>(adj, num_nodes, demands);
    cudaEventRecord(evJoin, s2);

    // flow branch (main stream)
    k_mlp<<<(NC+127)/128, 128>>>(0, dec_W1, dec_b1, dec_W2, dec_b2);
    k_inattn <<<BV/8, 256>>>(in_idx, inv_adj, adj, num_nodes);
    k_revnorm<<<BV/8, 256>>>(rev_idx, adj, num_nodes);
    k_flow<<<BB, 1024, FLOW_SMEM>>>(demands, inv_adj, in_idx, num_nodes);

    // join, then finalize
    cudaStreamWaitEvent(0, evJoin, 0);
    k_finalize<<<1, 256>>>(out);
}